// round 11
// baseline (speedup 1.0000x reference)
#include <cuda_runtime.h>
#include <cuda_bf16.h>
#include <cstdint>
#include <math.h>

#define NB 256
#define NTH 32
#define NTF 16
#define NS 512
#define NA 128
#define NF 1024
#define NG 3072
#define NT 65

typedef __nv_bfloat16 bf16;

// ------------------------------ scratch globals -------------------------------
__device__ float g_gi [(size_t)NT * NB * NG];
__device__ float g_fxg[(size_t)NB * NTF * NG];
__device__ float g_H  [4 * NB * NF];
__device__ bf16 g_H_hi[4 * NB * NF], g_H_lo[4 * NB * NF];
__device__ bf16 g_xs_hi [(size_t)NT * NB * NF], g_xs_lo [(size_t)NT * NB * NF];
__device__ bf16 g_seq_hi[(size_t)NT * NB * NF], g_seq_lo[(size_t)NT * NB * NF];
__device__ bf16 g_x_hi [NB * NF], g_x_lo [NB * NF];
__device__ bf16 g_fx_hi[NB * NTF * NF], g_fx_lo[NB * NTF * NF];
__device__ bf16 g_so_hi[NB * NS], g_so_lo[NB * NS];
__device__ bf16 g_sb_hi[NB * NTH * NF], g_sb_lo[NB * NTH * NF];
__device__ bf16 g_ab_hi[NB * NTH * NF], g_ab_lo[NB * NTH * NF];
__device__ bf16 g_hs_hi[NB * NTH * NS], g_hs_lo[NB * NTH * NS];
__device__ bf16 g_ha_hi[NB * NTH * NA], g_ha_lo[NB * NTH * NA];
__device__ bf16 g_ps_hi[NB * NS],       g_ps_lo[NB * NS];
__device__ bf16 g_fa_hi[NB * NTF * NA], g_fa_lo[NB * NTF * NA];
__device__ bf16 g_Ws_hi [NF * NS],     g_Ws_lo [NF * NS];
__device__ bf16 g_Wa_hi [NF * NA],     g_Wa_lo [NF * NA];
__device__ bf16 g_Wih_hi[2 * NG * NF], g_Wih_lo[2 * NG * NF];
__device__ bf16 g_Whh_hi[2 * NG * NF], g_Whh_lo[2 * NG * NF];
__device__ bf16 g_Ws2_hi[NS * NF],     g_Ws2_lo[NS * NF];

// ------------------------------- helpers --------------------------------------
__device__ __forceinline__ uint32_t smem_u32(const void* p) {
    uint32_t a;
    asm("{ .reg .u64 t; cvta.to.shared.u64 t, %1; cvt.u32.u64 %0, t; }" : "=r"(a) : "l"(p));
    return a;
}
#define CPA(d, s) asm volatile("cp.async.cg.shared.global [%0], [%1], 16;" :: "r"(d), "l"(s))
#define CPA_COMMIT() asm volatile("cp.async.commit_group;" ::: "memory")
#define CPA_WAIT1() asm volatile("cp.async.wait_group 1;" ::: "memory")
#define CPA_WAIT0() asm volatile("cp.async.wait_group 0;" ::: "memory")

#define LDSM4(r0, r1, r2, r3, a) \
    asm volatile("ldmatrix.sync.aligned.m8n8.x4.shared.b16 {%0,%1,%2,%3}, [%4];" \
                 : "=r"(r0), "=r"(r1), "=r"(r2), "=r"(r3) : "r"(a))
#define LDSM2(r0, r1, a) \
    asm volatile("ldmatrix.sync.aligned.m8n8.x2.shared.b16 {%0,%1}, [%2];" \
                 : "=r"(r0), "=r"(r1) : "r"(a))

__device__ __forceinline__ void mma4(float* d, const uint32_t* a, uint32_t b0, uint32_t b1) {
    asm volatile(
        "mma.sync.aligned.m16n8k16.row.col.f32.bf16.bf16.f32 "
        "{%0,%1,%2,%3},{%4,%5,%6,%7},{%8,%9},{%0,%1,%2,%3};"
        : "+f"(d[0]), "+f"(d[1]), "+f"(d[2]), "+f"(d[3])
        : "r"(a[0]), "r"(a[1]), "r"(a[2]), "r"(a[3]), "r"(b0), "r"(b1));
}

// ------------------------- generic GEMM (parallel parts) -----------------------
struct GP {
    const bf16 *Ah, *Al, *Wh, *Wl;
    const float* bias;
    float* C;
    bf16 *Ohi, *Olo;
    long lda, ldc, ldo;
};

// 128 threads / 4 warps.  Block 128 x BN.  Warp tile 64 x (BN/2).  ldmatrix frags.
// K-chunk 32, row stride 80B, 2-stage: SMEM <= 82KB -> 2 CTAs/SM occupancy.
#define RSG 80
template<int BN, int MODE>
__global__ __launch_bounds__(128)
void mma_gemm(GP p, int K)
{
    extern __shared__ __align__(16) char sm[];
    constexpr int APL = 128 * RSG;
    constexpr int BPL = BN * RSG;
    constexpr int STAGE = 2 * APL + 2 * BPL;
    constexpr int WNT = BN / 16;              // n-tiles (8 cols) per warp
    constexpr int NPAIR = WNT / 2;

    const int tid = threadIdx.x, lane = tid & 31, warp = tid >> 5;
    const int wm = warp & 1, wn = warp >> 1;
    const int m0 = blockIdx.y * 128, n0 = blockIdx.x * BN;
    const uint32_t sb = smem_u32(sm);
    const int lq = lane >> 2, lr = lane & 3;
    const int r8 = lane & 7;

    float acc[4][WNT][4];
    #pragma unroll
    for (int i = 0; i < 4; i++)
        #pragma unroll
        for (int j = 0; j < WNT; j++)
            #pragma unroll
            for (int q = 0; q < 4; q++) acc[i][j][q] = 0.f;

    auto load_stage = [&](int s, int k0) {
        uint32_t ab = sb + s * STAGE;
        #pragma unroll
        for (int v = tid; v < 512; v += 128) {
            int row = v >> 2, q = v & 3;
            size_t g = (size_t)(m0 + row) * p.lda + k0 + q * 8;
            uint32_t d = ab + row * RSG + q * 16;
            CPA(d, p.Ah + g);
            CPA(d + APL, p.Al + g);
        }
        #pragma unroll
        for (int v = tid; v < BN * 4; v += 128) {
            int row = v >> 2, q = v & 3;
            size_t g = (size_t)(n0 + row) * K + k0 + q * 8;
            uint32_t d = ab + 2 * APL + row * RSG + q * 16;
            CPA(d, p.Wh + g);
            CPA(d + BPL, p.Wl + g);
        }
    };

    const int NC = K >> 5;                    // 32-wide chunks
    load_stage(0, 0);
    CPA_COMMIT();

    for (int c = 0; c < NC; c++) {
        if (c + 1 < NC) { load_stage((c + 1) & 1, (c + 1) << 5); CPA_COMMIT(); CPA_WAIT1(); }
        else           { CPA_WAIT0(); }
        __syncthreads();

        const int s = c & 1;
        uint32_t aH = sb + s * STAGE, aL = aH + APL, bH = aL + APL, bL = bH + BPL;
        #pragma unroll
        for (int kk = 0; kk < 2; kk++) {
            const uint32_t aRow = (uint32_t)(wm * 64 + ((lane >> 3) & 1) * 8 + r8);
            const uint32_t aCol = (uint32_t)(kk * 32 + ((lane >> 4) & 1) * 16);
            uint32_t ah[4][4], al[4][4];
            #pragma unroll
            for (int mt = 0; mt < 4; mt++) {
                uint32_t ad = (aRow + mt * 16) * RSG + aCol;
                LDSM4(ah[mt][0], ah[mt][1], ah[mt][2], ah[mt][3], aH + ad);
                LDSM4(al[mt][0], al[mt][1], al[mt][2], al[mt][3], aL + ad);
            }
            uint32_t bh[NPAIR][4], bl[NPAIR][4];
            const uint32_t bCol = (uint32_t)(kk * 32 + ((lane >> 3) & 1) * 16);
            #pragma unroll
            for (int np = 0; np < NPAIR; np++) {
                uint32_t bRow = (uint32_t)(wn * (BN / 2) + np * 16 + ((lane >> 4) & 1) * 8 + r8);
                uint32_t bd = bRow * RSG + bCol;
                LDSM4(bh[np][0], bh[np][1], bh[np][2], bh[np][3], bH + bd);
                LDSM4(bl[np][0], bl[np][1], bl[np][2], bl[np][3], bL + bd);
            }
            #pragma unroll
            for (int np = 0; np < NPAIR; np++) {
                #pragma unroll
                for (int sd = 0; sd < 2; sd++) {
                    int nt = np * 2 + sd;
                    #pragma unroll
                    for (int mt = 0; mt < 4; mt++) {
                        mma4(acc[mt][nt], ah[mt], bh[np][sd * 2], bh[np][sd * 2 + 1]);
                        mma4(acc[mt][nt], ah[mt], bl[np][sd * 2], bl[np][sd * 2 + 1]);
                        mma4(acc[mt][nt], al[mt], bh[np][sd * 2], bh[np][sd * 2 + 1]);
                    }
                }
            }
        }
        __syncthreads();
    }

    #pragma unroll
    for (int mt = 0; mt < 4; mt++) {
        #pragma unroll
        for (int nt = 0; nt < WNT; nt++) {
            int gm = m0 + wm * 64 + mt * 16 + lq;
            int gn = n0 + wn * (BN / 2) + nt * 8 + lr * 2;
            float* a = acc[mt][nt];
            if (MODE == 0) {
                float2 v0; v0.x = a[0]; v0.y = a[1];
                float2 v1; v1.x = a[2]; v1.y = a[3];
                *reinterpret_cast<float2*>(p.C + (size_t)gm * p.ldc + gn) = v0;
                *reinterpret_cast<float2*>(p.C + (size_t)(gm + 8) * p.ldc + gn) = v1;
            } else {
                float b0 = p.bias[gn], b1 = p.bias[gn + 1];
                float v00 = tanhf(a[0] + b0), v01 = tanhf(a[1] + b1);
                float v10 = tanhf(a[2] + b0), v11 = tanhf(a[3] + b1);
                __nv_bfloat162 h0, l0, h1, l1;
                h0.x = __float2bfloat16(v00); h0.y = __float2bfloat16(v01);
                l0.x = __float2bfloat16(v00 - __bfloat162float(h0.x));
                l0.y = __float2bfloat16(v01 - __bfloat162float(h0.y));
                h1.x = __float2bfloat16(v10); h1.y = __float2bfloat16(v11);
                l1.x = __float2bfloat16(v10 - __bfloat162float(h1.x));
                l1.y = __float2bfloat16(v11 - __bfloat162float(h1.y));
                *reinterpret_cast<__nv_bfloat162*>(p.Ohi + (size_t)gm * p.ldo + gn) = h0;
                *reinterpret_cast<__nv_bfloat162*>(p.Olo + (size_t)gm * p.ldo + gn) = l0;
                *reinterpret_cast<__nv_bfloat162*>(p.Ohi + (size_t)(gm + 8) * p.ldo + gn) = h1;
                *reinterpret_cast<__nv_bfloat162*>(p.Olo + (size_t)(gm + 8) * p.ldo + gn) = l1;
                if (MODE == 3) {
                    float2 v0; v0.x = v00; v0.y = v01;
                    float2 v1; v1.x = v10; v1.y = v11;
                    *reinterpret_cast<float2*>(p.C + (size_t)gm * p.ldc + gn) = v0;
                    *reinterpret_cast<float2*>(p.C + (size_t)(gm + 8) * p.ldc + gn) = v1;
                }
            }
        }
    }
}

// ------------------- fused GRU step: gh GEMM (+gi GEMM) + gates ----------------
// 128 threads / 4 warps.  Block tile: 64 batch rows x (32 f x 3 gates = 96).
// Warp wn owns 8-wide f-group x 3 gates.  ldmatrix frags.  Grid (32, 4).
__device__ __forceinline__ void gs_compute(uint32_t aH, uint32_t aL, uint32_t bH, uint32_t bL,
                                           int wn, int lane, int kk, float (*acc)[3][4])
{
    const int r8 = lane & 7;
    const uint32_t aRow = (uint32_t)(((lane >> 3) & 1) * 8 + r8);
    const uint32_t aCol = (uint32_t)(kk * 32 + ((lane >> 4) & 1) * 16);
    uint32_t ah[4][4], al[4][4];
    #pragma unroll
    for (int mt = 0; mt < 4; mt++) {
        uint32_t ad = (aRow + mt * 16) * 144 + aCol;
        LDSM4(ah[mt][0], ah[mt][1], ah[mt][2], ah[mt][3], aH + ad);
        LDSM4(al[mt][0], al[mt][1], al[mt][2], al[mt][3], aL + ad);
    }
    uint32_t bh[6], bl[6];
    const uint32_t bCol = (uint32_t)(kk * 32 + ((lane >> 3) & 1) * 16);
    {
        uint32_t bRow = (uint32_t)(wn * 24 + ((lane >> 4) & 1) * 8 + r8);
        uint32_t bd = bRow * 144 + bCol;
        LDSM4(bh[0], bh[1], bh[2], bh[3], bH + bd);
        LDSM4(bl[0], bl[1], bl[2], bl[3], bL + bd);
    }
    {
        uint32_t bRow = (uint32_t)(wn * 24 + 16 + r8);
        uint32_t bd = bRow * 144 + bCol;
        LDSM2(bh[4], bh[5], bH + bd);
        LDSM2(bl[4], bl[5], bL + bd);
    }
    #pragma unroll
    for (int nt = 0; nt < 3; nt++) {
        uint32_t bh0 = bh[nt * 2], bh1 = bh[nt * 2 + 1];
        uint32_t bl0 = bl[nt * 2], bl1 = bl[nt * 2 + 1];
        #pragma unroll
        for (int mt = 0; mt < 4; mt++) {
            mma4(acc[mt][nt], ah[mt], bh0, bh1);
            mma4(acc[mt][nt], ah[mt], bl0, bl1);
            mma4(acc[mt][nt], al[mt], bh0, bh1);
        }
    }
}

template<int DUAL, int WSEQ>
__global__ __launch_bounds__(128)
void gru_step(const bf16* __restrict__ Hh, const bf16* __restrict__ Hl,
              const bf16* __restrict__ Wh_h, const bf16* __restrict__ Wh_l,
              const bf16* __restrict__ Xh, const bf16* __restrict__ Xl,
              const bf16* __restrict__ Wi_h, const bf16* __restrict__ Wi_l,
              const float* __restrict__ giB, long giS,
              const float* __restrict__ bih, const float* __restrict__ bhh,
              const float* __restrict__ hOld,
              float* __restrict__ hNew, bf16* __restrict__ nhi, bf16* __restrict__ nlo,
              bf16* __restrict__ shi, bf16* __restrict__ slo)
{
    extern __shared__ __align__(16) char sm[];
    constexpr int APL = 64 * 144, BPL = 96 * 144;
    constexpr int NP = DUAL ? 4 : 2;
    constexpr int STAGE = NP * (APL + BPL);

    const int tid = threadIdx.x, lane = tid & 31, wn = tid >> 5;
    const int lq = lane >> 2, lr = lane & 3;
    const int f0 = blockIdx.x * 32, m0 = blockIdx.y * 64;
    const uint32_t sb = smem_u32(sm);

    float acch[4][3][4];
    float acci[4][3][4];
    #pragma unroll
    for (int i = 0; i < 4; i++)
        #pragma unroll
        for (int j = 0; j < 3; j++)
            #pragma unroll
            for (int q = 0; q < 4; q++) { acch[i][j][q] = 0.f; acci[i][j][q] = 0.f; }

    auto load_stage = [&](int s, int k0) {
        uint32_t base = sb + s * STAGE;
        #pragma unroll
        for (int v = tid; v < 512; v += 128) {
            int row = v >> 3, q = v & 7;
            size_t g = (size_t)(m0 + row) * NF + k0 + q * 8;
            uint32_t d = base + row * 144 + q * 16;
            CPA(d, Hh + g);
            CPA(d + APL, Hl + g);
            if (DUAL) { CPA(d + 2 * APL, Xh + g); CPA(d + 3 * APL, Xl + g); }
        }
        uint32_t bb = base + NP * APL;
        #pragma unroll
        for (int v = tid; v < 768; v += 128) {
            int rr = v >> 3, q8 = v & 7;
            int qq = rr / 24, rem = rr - qq * 24;
            int g = rem >> 3, u = rem & 7;
            size_t R = (size_t)(g * 1024 + f0 + qq * 8 + u) * NF + k0 + q8 * 8;
            uint32_t d = bb + rr * 144 + q8 * 16;
            CPA(d, Wh_h + R);
            CPA(d + BPL, Wh_l + R);
            if (DUAL) { CPA(d + 2 * BPL, Wi_h + R); CPA(d + 3 * BPL, Wi_l + R); }
        }
    };

    const int NC = NF >> 6;          // 16
    load_stage(0, 0);
    CPA_COMMIT();

    for (int c = 0; c < NC; c++) {
        if (c + 1 < NC) { load_stage((c + 1) & 1, (c + 1) << 6); CPA_COMMIT(); CPA_WAIT1(); }
        else           { CPA_WAIT0(); }
        __syncthreads();

        uint32_t base = sb + (c & 1) * STAGE;
        uint32_t bb = base + NP * APL;
        #pragma unroll
        for (int kk = 0; kk < 4; kk++) {
            gs_compute(base, base + APL, bb, bb + BPL, wn, lane, kk, acch);
            if (DUAL)
                gs_compute(base + 2 * APL, base + 3 * APL,
                           bb + 2 * BPL, bb + 3 * BPL, wn, lane, kk, acci);
        }
        __syncthreads();
    }

    // ---- fused GRU gate epilogue ----
    const int fc = f0 + wn * 8 + lr * 2;     // this thread's f (col pair fc, fc+1)
    float bi[3][2], bh_[3][2];
    #pragma unroll
    for (int g = 0; g < 3; g++) {
        bi[g][0]  = bih[g * 1024 + fc];  bi[g][1]  = bih[g * 1024 + fc + 1];
        bh_[g][0] = bhh[g * 1024 + fc];  bh_[g][1] = bhh[g * 1024 + fc + 1];
    }
    #pragma unroll
    for (int mt = 0; mt < 4; mt++) {
        #pragma unroll
        for (int half = 0; half < 2; half++) {
            int b = m0 + mt * 16 + lq + half * 8;
            float o[2];
            #pragma unroll
            for (int cidx = 0; cidx < 2; cidx++) {
                int k = half * 2 + cidx;
                int f = fc + cidx;
                float hr = acch[mt][0][k], hz = acch[mt][1][k], hn = acch[mt][2][k];
                float ir, iz, in_;
                if (DUAL) {
                    ir = acci[mt][0][k]; iz = acci[mt][1][k]; in_ = acci[mt][2][k];
                } else {
                    const float* gp = giB + (size_t)b * giS;
                    ir = gp[f]; iz = gp[1024 + f]; in_ = gp[2048 + f];
                }
                float r = 1.f / (1.f + expf(-(ir + bi[0][cidx] + hr + bh_[0][cidx])));
                float z = 1.f / (1.f + expf(-(iz + bi[1][cidx] + hz + bh_[1][cidx])));
                float n = tanhf(in_ + bi[2][cidx] + r * (hn + bh_[2][cidx]));
                float ho = hOld[(size_t)b * NF + f];
                o[cidx] = (1.f - z) * n + z * ho;
            }
            float2 o2; o2.x = o[0]; o2.y = o[1];
            *reinterpret_cast<float2*>(hNew + (size_t)b * NF + fc) = o2;
            __nv_bfloat162 hh, ll;
            hh.x = __float2bfloat16(o[0]); hh.y = __float2bfloat16(o[1]);
            ll.x = __float2bfloat16(o[0] - __bfloat162float(hh.x));
            ll.y = __float2bfloat16(o[1] - __bfloat162float(hh.y));
            *reinterpret_cast<__nv_bfloat162*>(nhi + (size_t)b * NF + fc) = hh;
            *reinterpret_cast<__nv_bfloat162*>(nlo + (size_t)b * NF + fc) = ll;
            if (WSEQ) {
                *reinterpret_cast<__nv_bfloat162*>(shi + (size_t)b * NF + fc) = hh;
                *reinterpret_cast<__nv_bfloat162*>(slo + (size_t)b * NF + fc) = ll;
            }
        }
    }
}

// ------------------------------ small kernels ----------------------------------
__global__ void interleave_k(const bf16* __restrict__ sh, const bf16* __restrict__ sl,
                             const bf16* __restrict__ ah, const bf16* __restrict__ al,
                             bf16* __restrict__ xh, bf16* __restrict__ xl)
{
    int i = blockIdx.x * blockDim.x + threadIdx.x;
    int t = i / (NB * NF / 2);
    int rem = i % (NB * NF / 2);
    int b = rem / (NF / 2), f2 = rem % (NF / 2);
    int u = t >> 1;
    size_t src = (size_t)(b * NTH + u) * (NF / 2) + f2;
    const uint32_t* ph = reinterpret_cast<const uint32_t*>((t & 1) ? ah : sh);
    const uint32_t* pl = reinterpret_cast<const uint32_t*>((t & 1) ? al : sl);
    reinterpret_cast<uint32_t*>(xh)[i] = ph[src];
    reinterpret_cast<uint32_t*>(xl)[i] = pl[src];
}

__global__ void rproj_k(const float* __restrict__ H1, const float* __restrict__ Wr,
                        const float* __restrict__ br, float* __restrict__ out_r, int step)
{
    __shared__ float red[256];
    int b = blockIdx.x;
    float p = 0.f;
    for (int k = threadIdx.x; k < NF; k += 256) p += H1[(size_t)b * NF + k] * Wr[k];
    red[threadIdx.x] = p;
    __syncthreads();
    for (int s = 128; s > 0; s >>= 1) {
        if (threadIdx.x < s) red[threadIdx.x] += red[threadIdx.x + s];
        __syncthreads();
    }
    if (threadIdx.x == 0)
        out_r[b * NTF + step] = 1.f / (1.f + expf(-(red[0] + br[0])));
}

__global__ void split_k(const float* __restrict__ x, bf16* __restrict__ hi,
                        bf16* __restrict__ lo, int n)
{
    int i = blockIdx.x * blockDim.x + threadIdx.x;
    if (i < n) {
        float v = x[i];
        bf16 h = __float2bfloat16(v);
        hi[i] = h;
        lo[i] = __float2bfloat16(v - __bfloat162float(h));
    }
}

__global__ void zeroH_k(float* h, bf16* hi, bf16* lo, int n)
{
    int i = blockIdx.x * blockDim.x + threadIdx.x;
    if (i < n) { h[i] = 0.f; hi[i] = __float2bfloat16(0.f); lo[i] = __float2bfloat16(0.f); }
}

// ----------------------------------- host --------------------------------------
static const int SMEM128 = 2 * (2 * 128 * RSG + 2 * 128 * RSG);   // 81920
static const int SMEM64  = 2 * (2 * 128 * RSG + 2 *  64 * RSG);   // 61440
static const int SMS     = 2 * 2 * (64 * 144 + 96 * 144);         // 92160
static const int SMD     = 2 * 4 * (64 * 144 + 96 * 144);         // 184320

static inline GP mkGP(const bf16* Ah, const bf16* Al, long lda,
                      const bf16* Wh, const bf16* Wl,
                      const float* bias, float* C, long ldc,
                      bf16* Ohi, bf16* Olo, long ldo)
{
    GP p; p.Ah = Ah; p.Al = Al; p.Wh = Wh; p.Wl = Wl; p.bias = bias;
    p.C = C; p.Ohi = Ohi; p.Olo = Olo; p.lda = lda; p.ldc = ldc; p.ldo = ldo;
    return p;
}

extern "C" void kernel_launch(void* const* d_in, const int* in_sizes, int n_in,
                              void* d_out, int out_size)
{
    (void)in_sizes; (void)n_in; (void)out_size;
    const float* history_s = (const float*)d_in[0];
    const float* history_a = (const float*)d_in[1];
    const float* present_s = (const float*)d_in[2];
    const float* future_a  = (const float*)d_in[3];
    const float* Ws  = (const float*)d_in[4];
    const float* bs  = (const float*)d_in[5];
    const float* Wa  = (const float*)d_in[6];
    const float* ba  = (const float*)d_in[7];
    const float* Wih = (const float*)d_in[8];
    const float* Whh = (const float*)d_in[9];
    const float* bih = (const float*)d_in[10];
    const float* bhh = (const float*)d_in[11];
    const float* Wr  = (const float*)d_in[12];
    const float* br  = (const float*)d_in[13];
    const float* Ws2 = (const float*)d_in[14];
    const float* bs2 = (const float*)d_in[15];

    float* out_r = (float*)d_out;
    float* out_s = (float*)d_out + NB * NTF;

    float *gi, *fxg, *H;
    bf16 *Hhi, *Hlo, *xshi, *xslo, *seqhi, *seqlo, *xhi, *xlo, *fxhi, *fxlo, *sohi, *solo;
    bf16 *sbhi, *sblo, *abhi, *ablo;
    bf16 *hshi, *hslo, *hahi, *halo, *pshi, *pslo, *fahi, *falo;
    bf16 *Wshi, *Wslo, *Wahi, *Walo, *Wihhi, *Wihlo, *Whhhi, *Whhlo, *Ws2hi, *Ws2lo;
    cudaGetSymbolAddress((void**)&gi, g_gi);     cudaGetSymbolAddress((void**)&fxg, g_fxg);
    cudaGetSymbolAddress((void**)&H, g_H);
    cudaGetSymbolAddress((void**)&Hhi, g_H_hi);  cudaGetSymbolAddress((void**)&Hlo, g_H_lo);
    cudaGetSymbolAddress((void**)&xshi, g_xs_hi); cudaGetSymbolAddress((void**)&xslo, g_xs_lo);
    cudaGetSymbolAddress((void**)&seqhi, g_seq_hi); cudaGetSymbolAddress((void**)&seqlo, g_seq_lo);
    cudaGetSymbolAddress((void**)&xhi, g_x_hi);  cudaGetSymbolAddress((void**)&xlo, g_x_lo);
    cudaGetSymbolAddress((void**)&fxhi, g_fx_hi); cudaGetSymbolAddress((void**)&fxlo, g_fx_lo);
    cudaGetSymbolAddress((void**)&sohi, g_so_hi); cudaGetSymbolAddress((void**)&solo, g_so_lo);
    cudaGetSymbolAddress((void**)&sbhi, g_sb_hi); cudaGetSymbolAddress((void**)&sblo, g_sb_lo);
    cudaGetSymbolAddress((void**)&abhi, g_ab_hi); cudaGetSymbolAddress((void**)&ablo, g_ab_lo);
    cudaGetSymbolAddress((void**)&hshi, g_hs_hi); cudaGetSymbolAddress((void**)&hslo, g_hs_lo);
    cudaGetSymbolAddress((void**)&hahi, g_ha_hi); cudaGetSymbolAddress((void**)&halo, g_ha_lo);
    cudaGetSymbolAddress((void**)&pshi, g_ps_hi); cudaGetSymbolAddress((void**)&pslo, g_ps_lo);
    cudaGetSymbolAddress((void**)&fahi, g_fa_hi); cudaGetSymbolAddress((void**)&falo, g_fa_lo);
    cudaGetSymbolAddress((void**)&Wshi, g_Ws_hi); cudaGetSymbolAddress((void**)&Wslo, g_Ws_lo);
    cudaGetSymbolAddress((void**)&Wahi, g_Wa_hi); cudaGetSymbolAddress((void**)&Walo, g_Wa_lo);
    cudaGetSymbolAddress((void**)&Wihhi, g_Wih_hi); cudaGetSymbolAddress((void**)&Wihlo, g_Wih_lo);
    cudaGetSymbolAddress((void**)&Whhhi, g_Whh_hi); cudaGetSymbolAddress((void**)&Whhlo, g_Whh_lo);
    cudaGetSymbolAddress((void**)&Ws2hi, g_Ws2_hi); cudaGetSymbolAddress((void**)&Ws2lo, g_Ws2_lo);

    cudaFuncSetAttribute(mma_gemm<128, 0>, cudaFuncAttributeMaxDynamicSharedMemorySize, SMEM128);
    cudaFuncSetAttribute(mma_gemm<128, 1>, cudaFuncAttributeMaxDynamicSharedMemorySize, SMEM128);
    cudaFuncSetAttribute(mma_gemm<64, 1>,  cudaFuncAttributeMaxDynamicSharedMemorySize, SMEM64);
    cudaFuncSetAttribute(mma_gemm<64, 3>,  cudaFuncAttributeMaxDynamicSharedMemorySize, SMEM64);
    cudaFuncSetAttribute(gru_step<0, 0>, cudaFuncAttributeMaxDynamicSharedMemorySize, SMS);
    cudaFuncSetAttribute(gru_step<0, 1>, cudaFuncAttributeMaxDynamicSharedMemorySize, SMS);
    cudaFuncSetAttribute(gru_step<1, 0>, cudaFuncAttributeMaxDynamicSharedMemorySize, SMD);

    auto split = [&](const float* x, bf16* hi, bf16* lo, long n) {
        split_k<<<(int)((n + 255) / 256), 256>>>(x, hi, lo, (int)n);
    };
    split(history_s, hshi, hslo, (long)NB * NTH * NS);
    split(history_a, hahi, halo, (long)NB * NTH * NA);
    split(present_s, pshi, pslo, (long)NB * NS);
    split(future_a,  fahi, falo, (long)NB * NTF * NA);
    split(Ws,  Wshi,  Wslo,  (long)NF * NS);
    split(Wa,  Wahi,  Walo,  (long)NF * NA);
    split(Wih, Wihhi, Wihlo, (long)2 * NG * NF);
    split(Whh, Whhhi, Whhlo, (long)2 * NG * NF);
    split(Ws2, Ws2hi, Ws2lo, (long)NS * NF);
    zeroH_k<<<(4 * NB * NF + 255) / 256, 256>>>(H, Hhi, Hlo, 4 * NB * NF);

    const bf16 *Wih0h = Wihhi, *Wih0l = Wihlo;
    const bf16 *Wih1h = Wihhi + (size_t)NG * NF, *Wih1l = Wihlo + (size_t)NG * NF;
    const bf16 *Whh0h = Whhhi, *Whh0l = Whhlo;
    const bf16 *Whh1h = Whhhi + (size_t)NG * NF, *Whh1l = Whhlo + (size_t)NG * NF;
    const float *bih0 = bih, *bih1 = bih + NG, *bhh0 = bhh, *bhh1 = bhh + NG;

    auto Hf  = [&](int l, int p) { return H   + (size_t)(l * 2 + p) * NB * NF; };
    auto Hfh = [&](int l, int p) { return Hhi + (size_t)(l * 2 + p) * NB * NF; };
    auto Hfl = [&](int l, int p) { return Hlo + (size_t)(l * 2 + p) * NB * NF; };
    int p0 = 0, p1 = 0;

    const dim3 GS(NF / 32, NB / 64);       // (32, 4) = 128 CTAs

    // embeddings (parallel)
    {   GP p = mkGP(hshi, hslo, NS, Wshi, Wslo, bs, nullptr, 0, sbhi, sblo, NF);
        mma_gemm<128, 1><<<dim3(NF / 128, (NB * NTH) / 128), 128, SMEM128>>>(p, NS); }
    {   GP p = mkGP(hahi, halo, NA, Wahi, Walo, ba, nullptr, 0, abhi, ablo, NF);
        mma_gemm<128, 1><<<dim3(NF / 128, (NB * NTH) / 128), 128, SMEM128>>>(p, NA); }
    {   GP p = mkGP(pshi, pslo, NS, Wshi, Wslo, bs, nullptr, 0,
                    xshi + (size_t)64 * NB * NF, xslo + (size_t)64 * NB * NF, NF);
        mma_gemm<64, 1><<<dim3(NF / 64, NB / 128), 128, SMEM64>>>(p, NS); }
    {   GP p = mkGP(fahi, falo, NA, Wahi, Walo, ba, nullptr, 0, fxhi, fxlo, NF);
        mma_gemm<128, 1><<<dim3(NF / 128, (NB * NTF) / 128), 128, SMEM128>>>(p, NA); }
    interleave_k<<<(64 * NB * NF / 2) / 256, 256>>>(sbhi, sblo, abhi, ablo, xshi, xslo);
    {   GP p = mkGP(fxhi, fxlo, NF, Wih0h, Wih0l, nullptr, fxg, NG, nullptr, nullptr, 0);
        mma_gemm<128, 0><<<dim3(NG / 128, (NB * NTF) / 128), 128, SMEM128>>>(p, NF); }

    // layer 0 over prefix
    {   GP p = mkGP(xshi, xslo, NF, Wih0h, Wih0l, nullptr, gi, NG, nullptr, nullptr, 0);
        mma_gemm<128, 0><<<dim3(NG / 128, (NT * NB) / 128), 128, SMEM128>>>(p, NF); }
    for (int t = 0; t < NT; t++) {
        gru_step<0, 1><<<GS, 128, SMS>>>(Hfh(0, p0), Hfl(0, p0), Whh0h, Whh0l,
            nullptr, nullptr, nullptr, nullptr,
            gi + (size_t)t * NB * NG, (long)NG, bih0, bhh0,
            Hf(0, p0), Hf(0, p0 ^ 1), Hfh(0, p0 ^ 1), Hfl(0, p0 ^ 1),
            seqhi + (size_t)t * NB * NF, seqlo + (size_t)t * NB * NF);
        p0 ^= 1;
    }
    // layer 1 over prefix
    {   GP p = mkGP(seqhi, seqlo, NF, Wih1h, Wih1l, nullptr, gi, NG, nullptr, nullptr, 0);
        mma_gemm<128, 0><<<dim3(NG / 128, (NT * NB) / 128), 128, SMEM128>>>(p, NF); }
    for (int t = 0; t < NT; t++) {
        gru_step<0, 0><<<GS, 128, SMS>>>(Hfh(1, p1), Hfl(1, p1), Whh1h, Whh1l,
            nullptr, nullptr, nullptr, nullptr,
            gi + (size_t)t * NB * NG, (long)NG, bih1, bhh1,
            Hf(1, p1), Hf(1, p1 ^ 1), Hfh(1, p1 ^ 1), Hfl(1, p1 ^ 1),
            nullptr, nullptr);
        p1 ^= 1;
    }

    auto dcell = [&](const bf16* Xh, const bf16* Xl, int layer) {
        int& pp = layer ? p1 : p0;
        gru_step<1, 0><<<GS, 128, SMD>>>(
            Hfh(layer, pp), Hfl(layer, pp),
            layer ? Whh1h : Whh0h, layer ? Whh1l : Whh0l,
            Xh, Xl, layer ? Wih1h : Wih0h, layer ? Wih1l : Wih0l,
            nullptr, 0, layer ? bih1 : bih0, layer ? bhh1 : bhh0,
            Hf(layer, pp), Hf(layer, pp ^ 1), Hfh(layer, pp ^ 1), Hfl(layer, pp ^ 1),
            nullptr, nullptr);
        pp ^= 1;
    };

    // future rollout
    for (int i = 0; i < NTF; i++) {
        gru_step<0, 0><<<GS, 128, SMS>>>(Hfh(0, p0), Hfl(0, p0), Whh0h, Whh0l,
            nullptr, nullptr, nullptr, nullptr,
            fxg + (size_t)i * NG, (long)NTF * NG, bih0, bhh0,
            Hf(0, p0), Hf(0, p0 ^ 1), Hfh(0, p0 ^ 1), Hfl(0, p0 ^ 1),
            nullptr, nullptr);
        p0 ^= 1;
        dcell(Hfh(0, p0), Hfl(0, p0), 1);

        rproj_k<<<NB, 256>>>(Hf(1, p1), Wr, br, out_r, i);
        {   GP p = mkGP(Hfh(1, p1), Hfl(1, p1), NF, Ws2hi, Ws2lo, bs2,
                        out_s + (size_t)i * NS, (long)NTF * NS, sohi, solo, NS);
            mma_gemm<64, 3><<<dim3(NS / 64, NB / 128), 128, SMEM64>>>(p, NF); }
        {   GP p = mkGP(sohi, solo, NS, Wshi, Wslo, bs, nullptr, 0, xhi, xlo, NF);
            mma_gemm<64, 1><<<dim3(NF / 64, NB / 128), 128, SMEM64>>>(p, NS); }
        dcell(xhi, xlo, 0);
        dcell(Hfh(0, p0), Hfl(0, p0), 1);
    }
}

// round 13
// speedup vs baseline: 1.0133x; 1.0133x over previous
#include <cuda_runtime.h>
#include <cuda_bf16.h>
#include <cstdint>
#include <math.h>

#define NB 256
#define NTH 32
#define NTF 16
#define NS 512
#define NA 128
#define NF 1024
#define NG 3072
#define NT 65

typedef __nv_bfloat16 bf16;

// ------------------------------ scratch globals -------------------------------
__device__ float g_gi [(size_t)NT * NB * NG];
__device__ float g_fxg[(size_t)NB * NTF * NG];
__device__ float g_H  [4 * NB * NF];
__device__ bf16 g_H_hi[4 * NB * NF], g_H_lo[4 * NB * NF];
__device__ bf16 g_xs_hi [(size_t)NT * NB * NF], g_xs_lo [(size_t)NT * NB * NF];
__device__ bf16 g_seq_hi[(size_t)NT * NB * NF], g_seq_lo[(size_t)NT * NB * NF];
__device__ bf16 g_x_hi [NB * NF], g_x_lo [NB * NF];
__device__ bf16 g_fx_hi[NB * NTF * NF], g_fx_lo[NB * NTF * NF];
__device__ bf16 g_so_hi[NB * NS], g_so_lo[NB * NS];
__device__ bf16 g_hs_hi[NB * NTH * NS], g_hs_lo[NB * NTH * NS];
__device__ bf16 g_ha_hi[NB * NTH * NA], g_ha_lo[NB * NTH * NA];
__device__ bf16 g_ps_hi[NB * NS],       g_ps_lo[NB * NS];
__device__ bf16 g_fa_hi[NB * NTF * NA], g_fa_lo[NB * NTF * NA];
__device__ bf16 g_Ws_hi [NF * NS],     g_Ws_lo [NF * NS];
__device__ bf16 g_Wa_hi [NF * NA],     g_Wa_lo [NF * NA];
__device__ bf16 g_Wih_hi[2 * NG * NF], g_Wih_lo[2 * NG * NF];
__device__ bf16 g_Whh_hi[2 * NG * NF], g_Whh_lo[2 * NG * NF];
__device__ bf16 g_Ws2_hi[NS * NF],     g_Ws2_lo[NS * NF];

// ------------------------------- helpers --------------------------------------
__device__ __forceinline__ uint32_t smem_u32(const void* p) {
    uint32_t a;
    asm("{ .reg .u64 t; cvta.to.shared.u64 t, %1; cvt.u32.u64 %0, t; }" : "=r"(a) : "l"(p));
    return a;
}
#define CPA(d, s) asm volatile("cp.async.cg.shared.global [%0], [%1], 16;" :: "r"(d), "l"(s))
#define CPA_COMMIT() asm volatile("cp.async.commit_group;" ::: "memory")
#define CPA_WAIT1() asm volatile("cp.async.wait_group 1;" ::: "memory")
#define CPA_WAIT0() asm volatile("cp.async.wait_group 0;" ::: "memory")

#define LDSM4(r0, r1, r2, r3, a) \
    asm volatile("ldmatrix.sync.aligned.m8n8.x4.shared.b16 {%0,%1,%2,%3}, [%4];" \
                 : "=r"(r0), "=r"(r1), "=r"(r2), "=r"(r3) : "r"(a))
#define LDSM2(r0, r1, a) \
    asm volatile("ldmatrix.sync.aligned.m8n8.x2.shared.b16 {%0,%1}, [%2];" \
                 : "=r"(r0), "=r"(r1) : "r"(a))

__device__ __forceinline__ void mma4(float* d, const uint32_t* a, uint32_t b0, uint32_t b1) {
    asm volatile(
        "mma.sync.aligned.m16n8k16.row.col.f32.bf16.bf16.f32 "
        "{%0,%1,%2,%3},{%4,%5,%6,%7},{%8,%9},{%0,%1,%2,%3};"
        : "+f"(d[0]), "+f"(d[1]), "+f"(d[2]), "+f"(d[3])
        : "r"(a[0]), "r"(a[1]), "r"(a[2]), "r"(a[3]), "r"(b0), "r"(b1));
}

// ------------------------- generic GEMM (parallel parts) -----------------------
struct GP {
    const bf16 *Ah, *Al, *Wh, *Wl;
    const float* bias;
    float* C;
    bf16 *Ohi, *Olo;
    long lda, ldc, ldo;
    int par;
};

// 128 threads / 4 warps.  Block 128 x BN.  Warp tile 64 x (BN/2).  ldmatrix frags.
// MODE 0: fp32 C.  MODE 1: tanh(+bias)->hi/lo.  MODE 2: MODE1 + prefix scatter
// (A row b*32+u -> out row (2u+par)*NB + b).  MODE 3: MODE1 + fp32 C.
template<int BN, int MODE>
__global__ __launch_bounds__(128)
void mma_gemm(GP p, int K)
{
    extern __shared__ __align__(16) char sm[];
    constexpr int APL = 128 * 144;
    constexpr int BPL = BN * 144;
    constexpr int STAGE = 2 * APL + 2 * BPL;
    constexpr int WNT = BN / 16;
    constexpr int NPAIR = WNT / 2;

    const int tid = threadIdx.x, lane = tid & 31, warp = tid >> 5;
    const int wm = warp & 1, wn = warp >> 1;
    const int m0 = blockIdx.y * 128, n0 = blockIdx.x * BN;
    const uint32_t sb = smem_u32(sm);
    const int lq = lane >> 2, lr = lane & 3;
    const int r8 = lane & 7;

    float acc[4][WNT][4];
    #pragma unroll
    for (int i = 0; i < 4; i++)
        #pragma unroll
        for (int j = 0; j < WNT; j++)
            #pragma unroll
            for (int q = 0; q < 4; q++) acc[i][j][q] = 0.f;

    auto load_stage = [&](int s, int k0) {
        uint32_t ab = sb + s * STAGE;
        #pragma unroll
        for (int v = tid; v < 1024; v += 128) {
            int row = v >> 3, q = v & 7;
            size_t g = (size_t)(m0 + row) * p.lda + k0 + q * 8;
            uint32_t d = ab + row * 144 + q * 16;
            CPA(d, p.Ah + g);
            CPA(d + APL, p.Al + g);
        }
        #pragma unroll
        for (int v = tid; v < BN * 8; v += 128) {
            int row = v >> 3, q = v & 7;
            size_t g = (size_t)(n0 + row) * K + k0 + q * 8;
            uint32_t d = ab + 2 * APL + row * 144 + q * 16;
            CPA(d, p.Wh + g);
            CPA(d + BPL, p.Wl + g);
        }
    };

    const int NC = K >> 6;
    load_stage(0, 0);
    CPA_COMMIT();

    for (int c = 0; c < NC; c++) {
        if (c + 1 < NC) { load_stage((c + 1) & 1, (c + 1) << 6); CPA_COMMIT(); CPA_WAIT1(); }
        else           { CPA_WAIT0(); }
        __syncthreads();

        const int s = c & 1;
        uint32_t aH = sb + s * STAGE, aL = aH + APL, bH = aL + APL, bL = bH + BPL;
        #pragma unroll
        for (int kk = 0; kk < 4; kk++) {
            const uint32_t aRow = (uint32_t)(wm * 64 + ((lane >> 3) & 1) * 8 + r8);
            const uint32_t aCol = (uint32_t)(kk * 32 + ((lane >> 4) & 1) * 16);
            uint32_t ah[4][4], al[4][4];
            #pragma unroll
            for (int mt = 0; mt < 4; mt++) {
                uint32_t ad = (aRow + mt * 16) * 144 + aCol;
                LDSM4(ah[mt][0], ah[mt][1], ah[mt][2], ah[mt][3], aH + ad);
                LDSM4(al[mt][0], al[mt][1], al[mt][2], al[mt][3], aL + ad);
            }
            uint32_t bh[NPAIR][4], bl[NPAIR][4];
            const uint32_t bCol = (uint32_t)(kk * 32 + ((lane >> 3) & 1) * 16);
            #pragma unroll
            for (int np = 0; np < NPAIR; np++) {
                uint32_t bRow = (uint32_t)(wn * (BN / 2) + np * 16 + ((lane >> 4) & 1) * 8 + r8);
                uint32_t bd = bRow * 144 + bCol;
                LDSM4(bh[np][0], bh[np][1], bh[np][2], bh[np][3], bH + bd);
                LDSM4(bl[np][0], bl[np][1], bl[np][2], bl[np][3], bL + bd);
            }
            #pragma unroll
            for (int np = 0; np < NPAIR; np++) {
                #pragma unroll
                for (int sd = 0; sd < 2; sd++) {
                    int nt = np * 2 + sd;
                    #pragma unroll
                    for (int mt = 0; mt < 4; mt++) {
                        mma4(acc[mt][nt], ah[mt], bh[np][sd * 2], bh[np][sd * 2 + 1]);
                        mma4(acc[mt][nt], ah[mt], bl[np][sd * 2], bl[np][sd * 2 + 1]);
                        mma4(acc[mt][nt], al[mt], bh[np][sd * 2], bh[np][sd * 2 + 1]);
                    }
                }
            }
        }
        __syncthreads();
    }

    #pragma unroll
    for (int mt = 0; mt < 4; mt++) {
        #pragma unroll
        for (int nt = 0; nt < WNT; nt++) {
            int gm = m0 + wm * 64 + mt * 16 + lq;
            int gn = n0 + wn * (BN / 2) + nt * 8 + lr * 2;
            float* a = acc[mt][nt];
            if (MODE == 0) {
                float2 v0; v0.x = a[0]; v0.y = a[1];
                float2 v1; v1.x = a[2]; v1.y = a[3];
                *reinterpret_cast<float2*>(p.C + (size_t)gm * p.ldc + gn) = v0;
                *reinterpret_cast<float2*>(p.C + (size_t)(gm + 8) * p.ldc + gn) = v1;
            } else {
                float b0 = p.bias[gn], b1 = p.bias[gn + 1];
                float v00 = tanhf(a[0] + b0), v01 = tanhf(a[1] + b1);
                float v10 = tanhf(a[2] + b0), v11 = tanhf(a[3] + b1);
                __nv_bfloat162 h0, l0, h1, l1;
                h0.x = __float2bfloat16(v00); h0.y = __float2bfloat16(v01);
                l0.x = __float2bfloat16(v00 - __bfloat162float(h0.x));
                l0.y = __float2bfloat16(v01 - __bfloat162float(h0.y));
                h1.x = __float2bfloat16(v10); h1.y = __float2bfloat16(v11);
                l1.x = __float2bfloat16(v10 - __bfloat162float(h1.x));
                l1.y = __float2bfloat16(v11 - __bfloat162float(h1.y));
                size_t row0, row1;
                if (MODE == 2) {
                    row0 = (size_t)(2 * (gm & 31) + p.par) * NB + (gm >> 5);
                    row1 = (size_t)(2 * ((gm + 8) & 31) + p.par) * NB + ((gm + 8) >> 5);
                } else {
                    row0 = (size_t)gm; row1 = (size_t)(gm + 8);
                }
                *reinterpret_cast<__nv_bfloat162*>(p.Ohi + row0 * p.ldo + gn) = h0;
                *reinterpret_cast<__nv_bfloat162*>(p.Olo + row0 * p.ldo + gn) = l0;
                *reinterpret_cast<__nv_bfloat162*>(p.Ohi + row1 * p.ldo + gn) = h1;
                *reinterpret_cast<__nv_bfloat162*>(p.Olo + row1 * p.ldo + gn) = l1;
                if (MODE == 3) {
                    float2 v0; v0.x = v00; v0.y = v01;
                    float2 v1; v1.x = v10; v1.y = v11;
                    *reinterpret_cast<float2*>(p.C + (size_t)gm * p.ldc + gn) = v0;
                    *reinterpret_cast<float2*>(p.C + (size_t)(gm + 8) * p.ldc + gn) = v1;
                }
            }
        }
    }
}

// ------------------- fused GRU step: gh GEMM (+gi GEMM) + gates ----------------
__device__ __forceinline__ void gs_compute(uint32_t aH, uint32_t aL, uint32_t bH, uint32_t bL,
                                           int wn, int lane, int kk, float (*acc)[3][4])
{
    const int r8 = lane & 7;
    const uint32_t aRow = (uint32_t)(((lane >> 3) & 1) * 8 + r8);
    const uint32_t aCol = (uint32_t)(kk * 32 + ((lane >> 4) & 1) * 16);
    uint32_t ah[4][4], al[4][4];
    #pragma unroll
    for (int mt = 0; mt < 4; mt++) {
        uint32_t ad = (aRow + mt * 16) * 144 + aCol;
        LDSM4(ah[mt][0], ah[mt][1], ah[mt][2], ah[mt][3], aH + ad);
        LDSM4(al[mt][0], al[mt][1], al[mt][2], al[mt][3], aL + ad);
    }
    uint32_t bh[6], bl[6];
    const uint32_t bCol = (uint32_t)(kk * 32 + ((lane >> 3) & 1) * 16);
    {
        uint32_t bRow = (uint32_t)(wn * 24 + ((lane >> 4) & 1) * 8 + r8);
        uint32_t bd = bRow * 144 + bCol;
        LDSM4(bh[0], bh[1], bh[2], bh[3], bH + bd);
        LDSM4(bl[0], bl[1], bl[2], bl[3], bL + bd);
    }
    {
        uint32_t bRow = (uint32_t)(wn * 24 + 16 + r8);
        uint32_t bd = bRow * 144 + bCol;
        LDSM2(bh[4], bh[5], bH + bd);
        LDSM2(bl[4], bl[5], bL + bd);
    }
    #pragma unroll
    for (int nt = 0; nt < 3; nt++) {
        uint32_t bh0 = bh[nt * 2], bh1 = bh[nt * 2 + 1];
        uint32_t bl0 = bl[nt * 2], bl1 = bl[nt * 2 + 1];
        #pragma unroll
        for (int mt = 0; mt < 4; mt++) {
            mma4(acc[mt][nt], ah[mt], bh0, bh1);
            mma4(acc[mt][nt], ah[mt], bl0, bl1);
            mma4(acc[mt][nt], al[mt], bh0, bh1);
        }
    }
}

template<int DUAL, int WSEQ>
__global__ __launch_bounds__(128)
void gru_step(const bf16* __restrict__ Hh, const bf16* __restrict__ Hl,
              const bf16* __restrict__ Wh_h, const bf16* __restrict__ Wh_l,
              const bf16* __restrict__ Xh, const bf16* __restrict__ Xl,
              const bf16* __restrict__ Wi_h, const bf16* __restrict__ Wi_l,
              const float* __restrict__ giB, long giS,
              const float* __restrict__ bih, const float* __restrict__ bhh,
              const float* __restrict__ hOld,
              float* __restrict__ hNew, bf16* __restrict__ nhi, bf16* __restrict__ nlo,
              bf16* __restrict__ shi, bf16* __restrict__ slo)
{
    extern __shared__ __align__(16) char sm[];
    constexpr int APL = 64 * 144, BPL = 96 * 144;
    constexpr int NP = DUAL ? 4 : 2;
    constexpr int STAGE = NP * (APL + BPL);

    const int tid = threadIdx.x, lane = tid & 31, wn = tid >> 5;
    const int lq = lane >> 2, lr = lane & 3;
    const int f0 = blockIdx.x * 32, m0 = blockIdx.y * 64;
    const uint32_t sb = smem_u32(sm);

    float acch[4][3][4];
    float acci[4][3][4];
    #pragma unroll
    for (int i = 0; i < 4; i++)
        #pragma unroll
        for (int j = 0; j < 3; j++)
            #pragma unroll
            for (int q = 0; q < 4; q++) { acch[i][j][q] = 0.f; acci[i][j][q] = 0.f; }

    auto load_stage = [&](int s, int k0) {
        uint32_t base = sb + s * STAGE;
        #pragma unroll
        for (int v = tid; v < 512; v += 128) {
            int row = v >> 3, q = v & 7;
            size_t g = (size_t)(m0 + row) * NF + k0 + q * 8;
            uint32_t d = base + row * 144 + q * 16;
            CPA(d, Hh + g);
            CPA(d + APL, Hl + g);
            if (DUAL) { CPA(d + 2 * APL, Xh + g); CPA(d + 3 * APL, Xl + g); }
        }
        uint32_t bb = base + NP * APL;
        #pragma unroll
        for (int v = tid; v < 768; v += 128) {
            int rr = v >> 3, q8 = v & 7;
            int qq = rr / 24, rem = rr - qq * 24;
            int g = rem >> 3, u = rem & 7;
            size_t R = (size_t)(g * 1024 + f0 + qq * 8 + u) * NF + k0 + q8 * 8;
            uint32_t d = bb + rr * 144 + q8 * 16;
            CPA(d, Wh_h + R);
            CPA(d + BPL, Wh_l + R);
            if (DUAL) { CPA(d + 2 * BPL, Wi_h + R); CPA(d + 3 * BPL, Wi_l + R); }
        }
    };

    const int NC = NF >> 6;          // 16
    load_stage(0, 0);
    CPA_COMMIT();

    for (int c = 0; c < NC; c++) {
        if (c + 1 < NC) { load_stage((c + 1) & 1, (c + 1) << 6); CPA_COMMIT(); CPA_WAIT1(); }
        else           { CPA_WAIT0(); }
        __syncthreads();

        uint32_t base = sb + (c & 1) * STAGE;
        uint32_t bb = base + NP * APL;
        #pragma unroll
        for (int kk = 0; kk < 4; kk++) {
            gs_compute(base, base + APL, bb, bb + BPL, wn, lane, kk, acch);
            if (DUAL)
                gs_compute(base + 2 * APL, base + 3 * APL,
                           bb + 2 * BPL, bb + 3 * BPL, wn, lane, kk, acci);
        }
        __syncthreads();
    }

    const int fc = f0 + wn * 8 + lr * 2;
    float bi[3][2], bh_[3][2];
    #pragma unroll
    for (int g = 0; g < 3; g++) {
        bi[g][0]  = bih[g * 1024 + fc];  bi[g][1]  = bih[g * 1024 + fc + 1];
        bh_[g][0] = bhh[g * 1024 + fc];  bh_[g][1] = bhh[g * 1024 + fc + 1];
    }
    #pragma unroll
    for (int mt = 0; mt < 4; mt++) {
        #pragma unroll
        for (int half = 0; half < 2; half++) {
            int b = m0 + mt * 16 + lq + half * 8;
            float o[2];
            #pragma unroll
            for (int cidx = 0; cidx < 2; cidx++) {
                int k = half * 2 + cidx;
                int f = fc + cidx;
                float hr = acch[mt][0][k], hz = acch[mt][1][k], hn = acch[mt][2][k];
                float ir, iz, in_;
                if (DUAL) {
                    ir = acci[mt][0][k]; iz = acci[mt][1][k]; in_ = acci[mt][2][k];
                } else {
                    const float* gp = giB + (size_t)b * giS;
                    ir = gp[f]; iz = gp[1024 + f]; in_ = gp[2048 + f];
                }
                float r = 1.f / (1.f + expf(-(ir + bi[0][cidx] + hr + bh_[0][cidx])));
                float z = 1.f / (1.f + expf(-(iz + bi[1][cidx] + hz + bh_[1][cidx])));
                float n = tanhf(in_ + bi[2][cidx] + r * (hn + bh_[2][cidx]));
                float ho = hOld[(size_t)b * NF + f];
                o[cidx] = (1.f - z) * n + z * ho;
            }
            float2 o2; o2.x = o[0]; o2.y = o[1];
            *reinterpret_cast<float2*>(hNew + (size_t)b * NF + fc) = o2;
            __nv_bfloat162 hh, ll;
            hh.x = __float2bfloat16(o[0]); hh.y = __float2bfloat16(o[1]);
            ll.x = __float2bfloat16(o[0] - __bfloat162float(hh.x));
            ll.y = __float2bfloat16(o[1] - __bfloat162float(hh.y));
            *reinterpret_cast<__nv_bfloat162*>(nhi + (size_t)b * NF + fc) = hh;
            *reinterpret_cast<__nv_bfloat162*>(nlo + (size_t)b * NF + fc) = ll;
            if (WSEQ) {
                *reinterpret_cast<__nv_bfloat162*>(shi + (size_t)b * NF + fc) = hh;
                *reinterpret_cast<__nv_bfloat162*>(slo + (size_t)b * NF + fc) = ll;
            }
        }
    }
}

// ------------------------------ small kernels ----------------------------------
struct SA {
    const float* s[9];
    bf16 *hi[9], *lo[9];
    long n[9];
    float* H;
    bf16 *Hh, *Hl;
    long nH;
    long total;
};

__global__ void split_all_k(SA a)
{
    long i = (long)blockIdx.x * blockDim.x + threadIdx.x;
    long stride = (long)gridDim.x * blockDim.x;
    for (; i < a.total; i += stride) {
        long r = i;
        int seg = 0;
        while (seg < 9 && r >= a.n[seg]) { r -= a.n[seg]; seg++; }
        if (seg < 9) {
            float v = a.s[seg][r];
            bf16 h = __float2bfloat16(v);
            a.hi[seg][r] = h;
            a.lo[seg][r] = __float2bfloat16(v - __bfloat162float(h));
        } else {
            a.H[r] = 0.f;
            a.Hh[r] = __float2bfloat16(0.f);
            a.Hl[r] = __float2bfloat16(0.f);
        }
    }
}

__global__ void rproj_k(const float* __restrict__ H1, const float* __restrict__ Wr,
                        const float* __restrict__ br, float* __restrict__ out_r, int step)
{
    __shared__ float red[256];
    int b = blockIdx.x;
    float p = 0.f;
    for (int k = threadIdx.x; k < NF; k += 256) p += H1[(size_t)b * NF + k] * Wr[k];
    red[threadIdx.x] = p;
    __syncthreads();
    for (int s = 128; s > 0; s >>= 1) {
        if (threadIdx.x < s) red[threadIdx.x] += red[threadIdx.x + s];
        __syncthreads();
    }
    if (threadIdx.x == 0)
        out_r[b * NTF + step] = 1.f / (1.f + expf(-(red[0] + br[0])));
}

// ----------------------------------- host --------------------------------------
static const int SMEM128 = 2 * (2 * 128 * 144 + 2 * 128 * 144);   // 147456
static const int SMEM64  = 2 * (2 * 128 * 144 + 2 *  64 * 144);   // 110592
static const int SMS     = 2 * 2 * (64 * 144 + 96 * 144);         // 92160
static const int SMD     = 2 * 4 * (64 * 144 + 96 * 144);         // 184320

static inline GP mkGP(const bf16* Ah, const bf16* Al, long lda,
                      const bf16* Wh, const bf16* Wl,
                      const float* bias, float* C, long ldc,
                      bf16* Ohi, bf16* Olo, long ldo, int par = 0)
{
    GP p; p.Ah = Ah; p.Al = Al; p.Wh = Wh; p.Wl = Wl; p.bias = bias;
    p.C = C; p.Ohi = Ohi; p.Olo = Olo; p.lda = lda; p.ldc = ldc; p.ldo = ldo;
    p.par = par;
    return p;
}

extern "C" void kernel_launch(void* const* d_in, const int* in_sizes, int n_in,
                              void* d_out, int out_size)
{
    (void)in_sizes; (void)n_in; (void)out_size;
    const float* history_s = (const float*)d_in[0];
    const float* history_a = (const float*)d_in[1];
    const float* present_s = (const float*)d_in[2];
    const float* future_a  = (const float*)d_in[3];
    const float* Ws  = (const float*)d_in[4];
    const float* bs  = (const float*)d_in[5];
    const float* Wa  = (const float*)d_in[6];
    const float* ba  = (const float*)d_in[7];
    const float* Wih = (const float*)d_in[8];
    const float* Whh = (const float*)d_in[9];
    const float* bih = (const float*)d_in[10];
    const float* bhh = (const float*)d_in[11];
    const float* Wr  = (const float*)d_in[12];
    const float* br  = (const float*)d_in[13];
    const float* Ws2 = (const float*)d_in[14];
    const float* bs2 = (const float*)d_in[15];

    float* out_r = (float*)d_out;
    float* out_s = (float*)d_out + NB * NTF;

    float *gi, *fxg, *H;
    bf16 *Hhi, *Hlo, *xshi, *xslo, *seqhi, *seqlo, *xhi, *xlo, *fxhi, *fxlo, *sohi, *solo;
    bf16 *hshi, *hslo, *hahi, *halo, *pshi, *pslo, *fahi, *falo;
    bf16 *Wshi, *Wslo, *Wahi, *Walo, *Wihhi, *Wihlo, *Whhhi, *Whhlo, *Ws2hi, *Ws2lo;
    cudaGetSymbolAddress((void**)&gi, g_gi);     cudaGetSymbolAddress((void**)&fxg, g_fxg);
    cudaGetSymbolAddress((void**)&H, g_H);
    cudaGetSymbolAddress((void**)&Hhi, g_H_hi);  cudaGetSymbolAddress((void**)&Hlo, g_H_lo);
    cudaGetSymbolAddress((void**)&xshi, g_xs_hi); cudaGetSymbolAddress((void**)&xslo, g_xs_lo);
    cudaGetSymbolAddress((void**)&seqhi, g_seq_hi); cudaGetSymbolAddress((void**)&seqlo, g_seq_lo);
    cudaGetSymbolAddress((void**)&xhi, g_x_hi);  cudaGetSymbolAddress((void**)&xlo, g_x_lo);
    cudaGetSymbolAddress((void**)&fxhi, g_fx_hi); cudaGetSymbolAddress((void**)&fxlo, g_fx_lo);
    cudaGetSymbolAddress((void**)&sohi, g_so_hi); cudaGetSymbolAddress((void**)&solo, g_so_lo);
    cudaGetSymbolAddress((void**)&hshi, g_hs_hi); cudaGetSymbolAddress((void**)&hslo, g_hs_lo);
    cudaGetSymbolAddress((void**)&hahi, g_ha_hi); cudaGetSymbolAddress((void**)&halo, g_ha_lo);
    cudaGetSymbolAddress((void**)&pshi, g_ps_hi); cudaGetSymbolAddress((void**)&pslo, g_ps_lo);
    cudaGetSymbolAddress((void**)&fahi, g_fa_hi); cudaGetSymbolAddress((void**)&falo, g_fa_lo);
    cudaGetSymbolAddress((void**)&Wshi, g_Ws_hi); cudaGetSymbolAddress((void**)&Wslo, g_Ws_lo);
    cudaGetSymbolAddress((void**)&Wahi, g_Wa_hi); cudaGetSymbolAddress((void**)&Walo, g_Wa_lo);
    cudaGetSymbolAddress((void**)&Wihhi, g_Wih_hi); cudaGetSymbolAddress((void**)&Wihlo, g_Wih_lo);
    cudaGetSymbolAddress((void**)&Whhhi, g_Whh_hi); cudaGetSymbolAddress((void**)&Whhlo, g_Whh_lo);
    cudaGetSymbolAddress((void**)&Ws2hi, g_Ws2_hi); cudaGetSymbolAddress((void**)&Ws2lo, g_Ws2_lo);

    cudaFuncSetAttribute(mma_gemm<128, 0>, cudaFuncAttributeMaxDynamicSharedMemorySize, SMEM128);
    cudaFuncSetAttribute(mma_gemm<128, 1>, cudaFuncAttributeMaxDynamicSharedMemorySize, SMEM128);
    cudaFuncSetAttribute(mma_gemm<128, 2>, cudaFuncAttributeMaxDynamicSharedMemorySize, SMEM128);
    cudaFuncSetAttribute(mma_gemm<64, 0>,  cudaFuncAttributeMaxDynamicSharedMemorySize, SMEM64);
    cudaFuncSetAttribute(mma_gemm<64, 1>,  cudaFuncAttributeMaxDynamicSharedMemorySize, SMEM64);
    cudaFuncSetAttribute(mma_gemm<64, 3>,  cudaFuncAttributeMaxDynamicSharedMemorySize, SMEM64);
    cudaFuncSetAttribute(gru_step<0, 0>, cudaFuncAttributeMaxDynamicSharedMemorySize, SMS);
    cudaFuncSetAttribute(gru_step<0, 1>, cudaFuncAttributeMaxDynamicSharedMemorySize, SMS);
    cudaFuncSetAttribute(gru_step<1, 0>, cudaFuncAttributeMaxDynamicSharedMemorySize, SMD);

    // ---- 1: merged split + zeroH ----
    {
        SA a;
        const float* srcs[9] = { history_s, history_a, present_s, future_a,
                                 Ws, Wa, Wih, Whh, Ws2 };
        bf16* his[9] = { hshi, hahi, pshi, fahi, Wshi, Wahi, Wihhi, Whhhi, Ws2hi };
        bf16* los[9] = { hslo, halo, pslo, falo, Wslo, Walo, Wihlo, Whhlo, Ws2lo };
        long ns[9] = { (long)NB * NTH * NS, (long)NB * NTH * NA, (long)NB * NS,
                       (long)NB * NTF * NA, (long)NF * NS, (long)NF * NA,
                       (long)2 * NG * NF, (long)2 * NG * NF, (long)NS * NF };
        long tot = 0;
        for (int k = 0; k < 9; k++) { a.s[k] = srcs[k]; a.hi[k] = his[k]; a.lo[k] = los[k]; a.n[k] = ns[k]; tot += ns[k]; }
        a.H = H; a.Hh = Hhi; a.Hl = Hlo; a.nH = (long)4 * NB * NF;
        a.total = tot + a.nH;
        split_all_k<<<4096, 256>>>(a);
    }

    const bf16 *Wih0h = Wihhi, *Wih0l = Wihlo;
    const bf16 *Wih1h = Wihhi + (size_t)NG * NF, *Wih1l = Wihlo + (size_t)NG * NF;
    const bf16 *Whh0h = Whhhi, *Whh0l = Whhlo;
    const bf16 *Whh1h = Whhhi + (size_t)NG * NF, *Whh1l = Whhlo + (size_t)NG * NF;
    const float *bih0 = bih, *bih1 = bih + NG, *bhh0 = bhh, *bhh1 = bhh + NG;

    auto Hf  = [&](int l, int p) { return H   + (size_t)(l * 2 + p) * NB * NF; };
    auto Hfh = [&](int l, int p) { return Hhi + (size_t)(l * 2 + p) * NB * NF; };
    auto Hfl = [&](int l, int p) { return Hlo + (size_t)(l * 2 + p) * NB * NF; };
    int p0 = 0, p1 = 0;

    const dim3 GS(NF / 32, NB / 64);

    // ---- 2,3: embeddings with fused prefix scatter ----
    {   GP p = mkGP(hshi, hslo, NS, Wshi, Wslo, bs, nullptr, 0, xshi, xslo, NF, 0);
        mma_gemm<128, 2><<<dim3(NF / 128, (NB * NTH) / 128), 128, SMEM128>>>(p, NS); }
    {   GP p = mkGP(hahi, halo, NA, Wahi, Walo, ba, nullptr, 0, xshi, xslo, NF, 1);
        mma_gemm<128, 2><<<dim3(NF / 128, (NB * NTH) / 128), 128, SMEM128>>>(p, NA); }

    // ---- 4: hoisted layer-0 gi over prefix slots 0..63 ----
    {   GP p = mkGP(xshi, xslo, NF, Wih0h, Wih0l, nullptr, gi, NG, nullptr, nullptr, 0);
        mma_gemm<128, 0><<<dim3(NG / 128, (64 * NB) / 128), 128, SMEM128>>>(p, NF); }

    // ---- 5: first GRU step (profiling target) ----
    gru_step<0, 1><<<GS, 128, SMS>>>(Hfh(0, p0), Hfl(0, p0), Whh0h, Whh0l,
        nullptr, nullptr, nullptr, nullptr,
        gi, (long)NG, bih0, bhh0,
        Hf(0, p0), Hf(0, p0 ^ 1), Hfh(0, p0 ^ 1), Hfl(0, p0 ^ 1),
        seqhi, seqlo);
    p0 ^= 1;

    // ---- 6,7: present embedding -> xs slot 64, and its gi ----
    {   GP p = mkGP(pshi, pslo, NS, Wshi, Wslo, bs, nullptr, 0,
                    xshi + (size_t)64 * NB * NF, xslo + (size_t)64 * NB * NF, NF);
        mma_gemm<64, 1><<<dim3(NF / 64, NB / 128), 128, SMEM64>>>(p, NS); }
    {   GP p = mkGP(xshi + (size_t)64 * NB * NF, xslo + (size_t)64 * NB * NF, NF,
                    Wih0h, Wih0l, nullptr, gi + (size_t)64 * NB * NG, NG,
                    nullptr, nullptr, 0);
        mma_gemm<64, 0><<<dim3(NG / 64, NB / 128), 128, SMEM64>>>(p, NF); }

    // ---- layer 0 over remaining prefix ----
    for (int t = 1; t < NT; t++) {
        gru_step<0, 1><<<GS, 128, SMS>>>(Hfh(0, p0), Hfl(0, p0), Whh0h, Whh0l,
            nullptr, nullptr, nullptr, nullptr,
            gi + (size_t)t * NB * NG, (long)NG, bih0, bhh0,
            Hf(0, p0), Hf(0, p0 ^ 1), Hfh(0, p0 ^ 1), Hfl(0, p0 ^ 1),
            seqhi + (size_t)t * NB * NF, seqlo + (size_t)t * NB * NF);
        p0 ^= 1;
    }

    // ---- future action embeddings + hoisted gi (independent of layer 1) ----
    {   GP p = mkGP(fahi, falo, NA, Wahi, Walo, ba, nullptr, 0, fxhi, fxlo, NF);
        mma_gemm<128, 1><<<dim3(NF / 128, (NB * NTF) / 128), 128, SMEM128>>>(p, NA); }
    {   GP p = mkGP(fxhi, fxlo, NF, Wih0h, Wih0l, nullptr, fxg, NG, nullptr, nullptr, 0);
        mma_gemm<128, 0><<<dim3(NG / 128, (NB * NTF) / 128), 128, SMEM128>>>(p, NF); }

    // ---- layer 1 over prefix ----
    {   GP p = mkGP(seqhi, seqlo, NF, Wih1h, Wih1l, nullptr, gi, NG, nullptr, nullptr, 0);
        mma_gemm<128, 0><<<dim3(NG / 128, (NT * NB) / 128), 128, SMEM128>>>(p, NF); }
    for (int t = 0; t < NT; t++) {
        gru_step<0, 0><<<GS, 128, SMS>>>(Hfh(1, p1), Hfl(1, p1), Whh1h, Whh1l,
            nullptr, nullptr, nullptr, nullptr,
            gi + (size_t)t * NB * NG, (long)NG, bih1, bhh1,
            Hf(1, p1), Hf(1, p1 ^ 1), Hfh(1, p1 ^ 1), Hfl(1, p1 ^ 1),
            nullptr, nullptr);
        p1 ^= 1;
    }

    auto dcell = [&](const bf16* Xh, const bf16* Xl, int layer) {
        int& pp = layer ? p1 : p0;
        gru_step<1, 0><<<GS, 128, SMD>>>(
            Hfh(layer, pp), Hfl(layer, pp),
            layer ? Whh1h : Whh0h, layer ? Whh1l : Whh0l,
            Xh, Xl, layer ? Wih1h : Wih0h, layer ? Wih1l : Wih0l,
            nullptr, 0, layer ? bih1 : bih0, layer ? bhh1 : bhh0,
            Hf(layer, pp), Hf(layer, pp ^ 1), Hfh(layer, pp ^ 1), Hfl(layer, pp ^ 1),
            nullptr, nullptr);
        pp ^= 1;
    };

    // ---- future rollout ----
    for (int i = 0; i < NTF; i++) {
        gru_step<0, 0><<<GS, 128, SMS>>>(Hfh(0, p0), Hfl(0, p0), Whh0h, Whh0l,
            nullptr, nullptr, nullptr, nullptr,
            fxg + (size_t)i * NG, (long)NTF * NG, bih0, bhh0,
            Hf(0, p0), Hf(0, p0 ^ 1), Hfh(0, p0 ^ 1), Hfl(0, p0 ^ 1),
            nullptr, nullptr);
        p0 ^= 1;
        dcell(Hfh(0, p0), Hfl(0, p0), 1);

        rproj_k<<<NB, 256>>>(Hf(1, p1), Wr, br, out_r, i);
        {   GP p = mkGP(Hfh(1, p1), Hfl(1, p1), NF, Ws2hi, Ws2lo, bs2,
                        out_s + (size_t)i * NS, (long)NTF * NS, sohi, solo, NS);
            mma_gemm<64, 3><<<dim3(NS / 64, NB / 128), 128, SMEM64>>>(p, NF); }
        {   GP p = mkGP(sohi, solo, NS, Wshi, Wslo, bs, nullptr, 0, xhi, xlo, NF);
            mma_gemm<64, 1><<<dim3(NF / 64, NB / 128), 128, SMEM64>>>(p, NS); }
        dcell(xhi, xlo, 0);
        dcell(Hfh(0, p0), Hfl(0, p0), 1);
    }
}

// round 15
// speedup vs baseline: 1.3613x; 1.3435x over previous
#include <cuda_runtime.h>
#include <cuda_fp16.h>
#include <cstdint>
#include <math.h>

#define NB 256
#define NTH 32
#define NTF 16
#define NS 512
#define NA 128
#define NF 1024
#define NG 3072
#define NT 65

typedef __half hf;

// ------------------------------ scratch globals -------------------------------
__device__ float g_gi [(size_t)NT * NB * NG];
__device__ float g_fxg[(size_t)NB * NTF * NG];
__device__ float g_H  [4 * NB * NF];
__device__ hf g_H_hi[4 * NB * NF], g_H_lo[4 * NB * NF];
__device__ hf g_xs_hi [(size_t)NT * NB * NF], g_xs_lo [(size_t)NT * NB * NF];
__device__ hf g_seq_hi[(size_t)NT * NB * NF], g_seq_lo[(size_t)NT * NB * NF];
__device__ hf g_x_hi [NB * NF], g_x_lo [NB * NF];
__device__ hf g_fx_hi[NB * NTF * NF], g_fx_lo[NB * NTF * NF];
__device__ hf g_so_hi[NB * NS], g_so_lo[NB * NS];
__device__ hf g_sb_hi[NB * NTH * NF], g_sb_lo[NB * NTH * NF];
__device__ hf g_ab_hi[NB * NTH * NF], g_ab_lo[NB * NTH * NF];
__device__ hf g_hs_hi[NB * NTH * NS], g_hs_lo[NB * NTH * NS];
__device__ hf g_ha_hi[NB * NTH * NA], g_ha_lo[NB * NTH * NA];
__device__ hf g_ps_hi[NB * NS],       g_ps_lo[NB * NS];
__device__ hf g_fa_hi[NB * NTF * NA], g_fa_lo[NB * NTF * NA];
__device__ hf g_Ws_h [NF * NS];
__device__ hf g_Wa_h [NF * NA];
__device__ hf g_Wih_h[2 * NG * NF];
__device__ hf g_Whh_h[2 * NG * NF];
__device__ hf g_Ws2_h[NS * NF];

// ------------------------------- helpers --------------------------------------
__device__ __forceinline__ uint32_t smem_u32(const void* p) {
    uint32_t a;
    asm("{ .reg .u64 t; cvta.to.shared.u64 t, %1; cvt.u32.u64 %0, t; }" : "=r"(a) : "l"(p));
    return a;
}
#define CPA(d, s) asm volatile("cp.async.cg.shared.global [%0], [%1], 16;" :: "r"(d), "l"(s))
#define CPA_COMMIT() asm volatile("cp.async.commit_group;" ::: "memory")
#define CPA_WAIT1() asm volatile("cp.async.wait_group 1;" ::: "memory")
#define CPA_WAIT0() asm volatile("cp.async.wait_group 0;" ::: "memory")

#define LDSM4(r0, r1, r2, r3, a) \
    asm volatile("ldmatrix.sync.aligned.m8n8.x4.shared.b16 {%0,%1,%2,%3}, [%4];" \
                 : "=r"(r0), "=r"(r1), "=r"(r2), "=r"(r3) : "r"(a))
#define LDSM2(r0, r1, a) \
    asm volatile("ldmatrix.sync.aligned.m8n8.x2.shared.b16 {%0,%1}, [%2];" \
                 : "=r"(r0), "=r"(r1) : "r"(a))

__device__ __forceinline__ void mma4(float* d, const uint32_t* a, uint32_t b0, uint32_t b1) {
    asm volatile(
        "mma.sync.aligned.m16n8k16.row.col.f32.f16.f16.f32 "
        "{%0,%1,%2,%3},{%4,%5,%6,%7},{%8,%9},{%0,%1,%2,%3};"
        : "+f"(d[0]), "+f"(d[1]), "+f"(d[2]), "+f"(d[3])
        : "r"(a[0]), "r"(a[1]), "r"(a[2]), "r"(a[3]), "r"(b0), "r"(b1));
}

__device__ __forceinline__ void split2(float v, hf& h, hf& l) {
    h = __float2half_rn(v);
    l = __float2half_rn(v - __half2float(h));
}

// ------------------------- generic GEMM (parallel parts) -----------------------
struct GP {
    const hf *Ah, *Al, *W;
    const float* bias;
    float* C;
    hf *Ohi, *Olo;
    long lda, ldc, ldo;
};

// 128 threads / 4 warps.  Block 128 x BN.  Warp tile 64 x (BN/2).  ldmatrix frags.
// fp16 2-pass: acc += ah*w + al*w.  MODE 0: fp32 C.  MODE 1: tanh(+bias)->hi/lo.
// MODE 3: MODE1 + fp32 C.
template<int BN, int MODE>
__global__ __launch_bounds__(128)
void mma_gemm(GP p, int K)
{
    extern __shared__ __align__(16) char sm[];
    constexpr int APL = 128 * 144;
    constexpr int BPL = BN * 144;
    constexpr int STAGE = 2 * APL + BPL;
    constexpr int WNT = BN / 16;
    constexpr int NPAIR = WNT / 2;

    const int tid = threadIdx.x, lane = tid & 31, warp = tid >> 5;
    const int wm = warp & 1, wn = warp >> 1;
    const int m0 = blockIdx.y * 128, n0 = blockIdx.x * BN;
    const uint32_t sb = smem_u32(sm);
    const int lq = lane >> 2, lr = lane & 3;
    const int r8 = lane & 7;

    float acc[4][WNT][4];
    #pragma unroll
    for (int i = 0; i < 4; i++)
        #pragma unroll
        for (int j = 0; j < WNT; j++)
            #pragma unroll
            for (int q = 0; q < 4; q++) acc[i][j][q] = 0.f;

    auto load_stage = [&](int s, int k0) {
        uint32_t ab = sb + s * STAGE;
        #pragma unroll
        for (int v = tid; v < 1024; v += 128) {
            int row = v >> 3, q = v & 7;
            size_t g = (size_t)(m0 + row) * p.lda + k0 + q * 8;
            uint32_t d = ab + row * 144 + q * 16;
            CPA(d, p.Ah + g);
            CPA(d + APL, p.Al + g);
        }
        #pragma unroll
        for (int v = tid; v < BN * 8; v += 128) {
            int row = v >> 3, q = v & 7;
            size_t g = (size_t)(n0 + row) * K + k0 + q * 8;
            CPA(ab + 2 * APL + row * 144 + q * 16, p.W + g);
        }
    };

    const int NC = K >> 6;
    load_stage(0, 0);
    CPA_COMMIT();

    for (int c = 0; c < NC; c++) {
        if (c + 1 < NC) { load_stage((c + 1) & 1, (c + 1) << 6); CPA_COMMIT(); CPA_WAIT1(); }
        else           { CPA_WAIT0(); }
        __syncthreads();

        const int s = c & 1;
        uint32_t aH = sb + s * STAGE, aL = aH + APL, bW = aL + APL;
        #pragma unroll
        for (int kk = 0; kk < 4; kk++) {
            const uint32_t aRow = (uint32_t)(wm * 64 + ((lane >> 3) & 1) * 8 + r8);
            const uint32_t aCol = (uint32_t)(kk * 32 + ((lane >> 4) & 1) * 16);
            uint32_t ah[4][4], al[4][4];
            #pragma unroll
            for (int mt = 0; mt < 4; mt++) {
                uint32_t ad = (aRow + mt * 16) * 144 + aCol;
                LDSM4(ah[mt][0], ah[mt][1], ah[mt][2], ah[mt][3], aH + ad);
                LDSM4(al[mt][0], al[mt][1], al[mt][2], al[mt][3], aL + ad);
            }
            uint32_t bh[NPAIR][4];
            const uint32_t bCol = (uint32_t)(kk * 32 + ((lane >> 3) & 1) * 16);
            #pragma unroll
            for (int np = 0; np < NPAIR; np++) {
                uint32_t bRow = (uint32_t)(wn * (BN / 2) + np * 16 + ((lane >> 4) & 1) * 8 + r8);
                LDSM4(bh[np][0], bh[np][1], bh[np][2], bh[np][3], bW + bRow * 144 + bCol);
            }
            #pragma unroll
            for (int np = 0; np < NPAIR; np++) {
                #pragma unroll
                for (int sd = 0; sd < 2; sd++) {
                    int nt = np * 2 + sd;
                    #pragma unroll
                    for (int mt = 0; mt < 4; mt++) {
                        mma4(acc[mt][nt], ah[mt], bh[np][sd * 2], bh[np][sd * 2 + 1]);
                        mma4(acc[mt][nt], al[mt], bh[np][sd * 2], bh[np][sd * 2 + 1]);
                    }
                }
            }
        }
        __syncthreads();
    }

    #pragma unroll
    for (int mt = 0; mt < 4; mt++) {
        #pragma unroll
        for (int nt = 0; nt < WNT; nt++) {
            int gm = m0 + wm * 64 + mt * 16 + lq;
            int gn = n0 + wn * (BN / 2) + nt * 8 + lr * 2;
            float* a = acc[mt][nt];
            if (MODE == 0) {
                float2 v0; v0.x = a[0]; v0.y = a[1];
                float2 v1; v1.x = a[2]; v1.y = a[3];
                *reinterpret_cast<float2*>(p.C + (size_t)gm * p.ldc + gn) = v0;
                *reinterpret_cast<float2*>(p.C + (size_t)(gm + 8) * p.ldc + gn) = v1;
            } else {
                float b0 = p.bias[gn], b1 = p.bias[gn + 1];
                float v00 = tanhf(a[0] + b0), v01 = tanhf(a[1] + b1);
                float v10 = tanhf(a[2] + b0), v11 = tanhf(a[3] + b1);
                __half2 h0, l0, h1, l1;
                split2(v00, h0.x, l0.x); split2(v01, h0.y, l0.y);
                split2(v10, h1.x, l1.x); split2(v11, h1.y, l1.y);
                *reinterpret_cast<__half2*>(p.Ohi + (size_t)gm * p.ldo + gn) = h0;
                *reinterpret_cast<__half2*>(p.Olo + (size_t)gm * p.ldo + gn) = l0;
                *reinterpret_cast<__half2*>(p.Ohi + (size_t)(gm + 8) * p.ldo + gn) = h1;
                *reinterpret_cast<__half2*>(p.Olo + (size_t)(gm + 8) * p.ldo + gn) = l1;
                if (MODE == 3) {
                    float2 v0; v0.x = v00; v0.y = v01;
                    float2 v1; v1.x = v10; v1.y = v11;
                    *reinterpret_cast<float2*>(p.C + (size_t)gm * p.ldc + gn) = v0;
                    *reinterpret_cast<float2*>(p.C + (size_t)(gm + 8) * p.ldc + gn) = v1;
                }
            }
        }
    }
}

// ------------------- fused GRU step: gh GEMM (+gi GEMM) + gates ----------------
// 128 threads / 4 warps.  Block tile: 64 batch rows x (32 f x 3 gates = 96).
__device__ __forceinline__ void gs_compute(uint32_t aH, uint32_t aL, uint32_t bW,
                                           int wn, int lane, int kk, float (*acc)[3][4])
{
    const int r8 = lane & 7;
    const uint32_t aRow = (uint32_t)(((lane >> 3) & 1) * 8 + r8);
    const uint32_t aCol = (uint32_t)(kk * 32 + ((lane >> 4) & 1) * 16);
    uint32_t ah[4][4], al[4][4];
    #pragma unroll
    for (int mt = 0; mt < 4; mt++) {
        uint32_t ad = (aRow + mt * 16) * 144 + aCol;
        LDSM4(ah[mt][0], ah[mt][1], ah[mt][2], ah[mt][3], aH + ad);
        LDSM4(al[mt][0], al[mt][1], al[mt][2], al[mt][3], aL + ad);
    }
    uint32_t bh[6];
    const uint32_t bCol = (uint32_t)(kk * 32 + ((lane >> 3) & 1) * 16);
    {
        uint32_t bRow = (uint32_t)(wn * 24 + ((lane >> 4) & 1) * 8 + r8);
        LDSM4(bh[0], bh[1], bh[2], bh[3], bW + bRow * 144 + bCol);
    }
    {
        uint32_t bRow = (uint32_t)(wn * 24 + 16 + r8);
        LDSM2(bh[4], bh[5], bW + bRow * 144 + bCol);
    }
    #pragma unroll
    for (int nt = 0; nt < 3; nt++) {
        uint32_t b0 = bh[nt * 2], b1 = bh[nt * 2 + 1];
        #pragma unroll
        for (int mt = 0; mt < 4; mt++) {
            mma4(acc[mt][nt], ah[mt], b0, b1);
            mma4(acc[mt][nt], al[mt], b0, b1);
        }
    }
}

template<int DUAL, int WSEQ>
__global__ __launch_bounds__(128)
void gru_step(const hf* __restrict__ Hh, const hf* __restrict__ Hl,
              const hf* __restrict__ Wh,
              const hf* __restrict__ Xh, const hf* __restrict__ Xl,
              const hf* __restrict__ Wi,
              const float* __restrict__ giB, long giS,
              const float* __restrict__ bih, const float* __restrict__ bhh,
              const float* __restrict__ hOld,
              float* __restrict__ hNew, hf* __restrict__ nhi, hf* __restrict__ nlo,
              hf* __restrict__ shi, hf* __restrict__ slo)
{
    extern __shared__ __align__(16) char sm[];
    constexpr int APL = 64 * 144, BPL = 96 * 144;
    constexpr int NPA = DUAL ? 4 : 2;
    constexpr int NPB = DUAL ? 2 : 1;
    constexpr int STAGE = NPA * APL + NPB * BPL;

    const int tid = threadIdx.x, lane = tid & 31, wn = tid >> 5;
    const int lq = lane >> 2, lr = lane & 3;
    const int f0 = blockIdx.x * 32, m0 = blockIdx.y * 64;
    const uint32_t sb = smem_u32(sm);

    float acch[4][3][4];
    float acci[4][3][4];
    #pragma unroll
    for (int i = 0; i < 4; i++)
        #pragma unroll
        for (int j = 0; j < 3; j++)
            #pragma unroll
            for (int q = 0; q < 4; q++) { acch[i][j][q] = 0.f; acci[i][j][q] = 0.f; }

    auto load_stage = [&](int s, int k0) {
        uint32_t base = sb + s * STAGE;
        #pragma unroll
        for (int v = tid; v < 512; v += 128) {
            int row = v >> 3, q = v & 7;
            size_t g = (size_t)(m0 + row) * NF + k0 + q * 8;
            uint32_t d = base + row * 144 + q * 16;
            CPA(d, Hh + g);
            CPA(d + APL, Hl + g);
            if (DUAL) { CPA(d + 2 * APL, Xh + g); CPA(d + 3 * APL, Xl + g); }
        }
        uint32_t bb = base + NPA * APL;
        #pragma unroll
        for (int v = tid; v < 768; v += 128) {
            int rr = v >> 3, q8 = v & 7;
            int qq = rr / 24, rem = rr - qq * 24;
            int g = rem >> 3, u = rem & 7;
            size_t R = (size_t)(g * 1024 + f0 + qq * 8 + u) * NF + k0 + q8 * 8;
            uint32_t d = bb + rr * 144 + q8 * 16;
            CPA(d, Wh + R);
            if (DUAL) CPA(d + BPL, Wi + R);
        }
    };

    const int NC = NF >> 6;          // 16
    load_stage(0, 0);
    CPA_COMMIT();

    for (int c = 0; c < NC; c++) {
        if (c + 1 < NC) { load_stage((c + 1) & 1, (c + 1) << 6); CPA_COMMIT(); CPA_WAIT1(); }
        else           { CPA_WAIT0(); }
        __syncthreads();

        uint32_t base = sb + (c & 1) * STAGE;
        uint32_t bb = base + NPA * APL;
        #pragma unroll
        for (int kk = 0; kk < 4; kk++) {
            gs_compute(base, base + APL, bb, wn, lane, kk, acch);
            if (DUAL)
                gs_compute(base + 2 * APL, base + 3 * APL, bb + BPL, wn, lane, kk, acci);
        }
        __syncthreads();
    }

    // ---- fused GRU gate epilogue ----
    const int fc = f0 + wn * 8 + lr * 2;
    float bi[3][2], bh_[3][2];
    #pragma unroll
    for (int g = 0; g < 3; g++) {
        bi[g][0]  = bih[g * 1024 + fc];  bi[g][1]  = bih[g * 1024 + fc + 1];
        bh_[g][0] = bhh[g * 1024 + fc];  bh_[g][1] = bhh[g * 1024 + fc + 1];
    }
    #pragma unroll
    for (int mt = 0; mt < 4; mt++) {
        #pragma unroll
        for (int half = 0; half < 2; half++) {
            int b = m0 + mt * 16 + lq + half * 8;
            float o[2];
            #pragma unroll
            for (int cidx = 0; cidx < 2; cidx++) {
                int k = half * 2 + cidx;
                int f = fc + cidx;
                float hr = acch[mt][0][k], hz = acch[mt][1][k], hn = acch[mt][2][k];
                float ir, iz, in_;
                if (DUAL) {
                    ir = acci[mt][0][k]; iz = acci[mt][1][k]; in_ = acci[mt][2][k];
                } else {
                    const float* gp = giB + (size_t)b * giS;
                    ir = gp[f]; iz = gp[1024 + f]; in_ = gp[2048 + f];
                }
                float r = 1.f / (1.f + expf(-(ir + bi[0][cidx] + hr + bh_[0][cidx])));
                float z = 1.f / (1.f + expf(-(iz + bi[1][cidx] + hz + bh_[1][cidx])));
                float n = tanhf(in_ + bi[2][cidx] + r * (hn + bh_[2][cidx]));
                float ho = hOld[(size_t)b * NF + f];
                o[cidx] = (1.f - z) * n + z * ho;
            }
            float2 o2; o2.x = o[0]; o2.y = o[1];
            *reinterpret_cast<float2*>(hNew + (size_t)b * NF + fc) = o2;
            __half2 hh, ll;
            split2(o[0], hh.x, ll.x);
            split2(o[1], hh.y, ll.y);
            *reinterpret_cast<__half2*>(nhi + (size_t)b * NF + fc) = hh;
            *reinterpret_cast<__half2*>(nlo + (size_t)b * NF + fc) = ll;
            if (WSEQ) {
                *reinterpret_cast<__half2*>(shi + (size_t)b * NF + fc) = hh;
                *reinterpret_cast<__half2*>(slo + (size_t)b * NF + fc) = ll;
            }
        }
    }
}

// ------------------------------ small kernels ----------------------------------
__global__ void interleave_k(const hf* __restrict__ sh, const hf* __restrict__ sl,
                             const hf* __restrict__ ah, const hf* __restrict__ al,
                             hf* __restrict__ xh, hf* __restrict__ xl)
{
    int i = blockIdx.x * blockDim.x + threadIdx.x;
    int t = i / (NB * NF / 2);
    int rem = i % (NB * NF / 2);
    int b = rem / (NF / 2), f2 = rem % (NF / 2);
    int u = t >> 1;
    size_t src = (size_t)(b * NTH + u) * (NF / 2) + f2;
    const uint32_t* ph = reinterpret_cast<const uint32_t*>((t & 1) ? ah : sh);
    const uint32_t* pl = reinterpret_cast<const uint32_t*>((t & 1) ? al : sl);
    reinterpret_cast<uint32_t*>(xh)[i] = ph[src];
    reinterpret_cast<uint32_t*>(xl)[i] = pl[src];
}

__global__ void rproj_k(const float* __restrict__ H1, const float* __restrict__ Wr,
                        const float* __restrict__ br, float* __restrict__ out_r, int step)
{
    __shared__ float red[256];
    int b = blockIdx.x;
    float p = 0.f;
    for (int k = threadIdx.x; k < NF; k += 256) p += H1[(size_t)b * NF + k] * Wr[k];
    red[threadIdx.x] = p;
    __syncthreads();
    for (int s = 128; s > 0; s >>= 1) {
        if (threadIdx.x < s) red[threadIdx.x] += red[threadIdx.x + s];
        __syncthreads();
    }
    if (threadIdx.x == 0)
        out_r[b * NTF + step] = 1.f / (1.f + expf(-(red[0] + br[0])));
}

__global__ void split2_k(const float* __restrict__ x, hf* __restrict__ hi,
                         hf* __restrict__ lo, int n)
{
    int i = blockIdx.x * blockDim.x + threadIdx.x;
    if (i < n) {
        hf h, l;
        split2(x[i], h, l);
        hi[i] = h; lo[i] = l;
    }
}

__global__ void split1_k(const float* __restrict__ x, hf* __restrict__ w, int n)
{
    int i = blockIdx.x * blockDim.x + threadIdx.x;
    if (i < n) w[i] = __float2half_rn(x[i]);
}

__global__ void zeroH_k(float* h, hf* hi, hf* lo, int n)
{
    int i = blockIdx.x * blockDim.x + threadIdx.x;
    if (i < n) { h[i] = 0.f; hi[i] = __float2half_rn(0.f); lo[i] = __float2half_rn(0.f); }
}

// ----------------------------------- host --------------------------------------
static const int SMEM128 = 2 * (2 * 128 * 144 + 128 * 144);   // 110592
static const int SMEM64  = 2 * (2 * 128 * 144 +  64 * 144);   // 92160
static const int SMS     = 2 * (2 * 64 * 144 + 96 * 144);     // 64512
static const int SMD     = 2 * (4 * 64 * 144 + 2 * 96 * 144); // 129024

static inline GP mkGP(const hf* Ah, const hf* Al, long lda, const hf* W,
                      const float* bias, float* C, long ldc,
                      hf* Ohi, hf* Olo, long ldo)
{
    GP p; p.Ah = Ah; p.Al = Al; p.W = W; p.bias = bias;
    p.C = C; p.Ohi = Ohi; p.Olo = Olo; p.lda = lda; p.ldc = ldc; p.ldo = ldo;
    return p;
}

extern "C" void kernel_launch(void* const* d_in, const int* in_sizes, int n_in,
                              void* d_out, int out_size)
{
    (void)in_sizes; (void)n_in; (void)out_size;
    const float* history_s = (const float*)d_in[0];
    const float* history_a = (const float*)d_in[1];
    const float* present_s = (const float*)d_in[2];
    const float* future_a  = (const float*)d_in[3];
    const float* Ws  = (const float*)d_in[4];
    const float* bs  = (const float*)d_in[5];
    const float* Wa  = (const float*)d_in[6];
    const float* ba  = (const float*)d_in[7];
    const float* Wih = (const float*)d_in[8];
    const float* Whh = (const float*)d_in[9];
    const float* bih = (const float*)d_in[10];
    const float* bhh = (const float*)d_in[11];
    const float* Wr  = (const float*)d_in[12];
    const float* br  = (const float*)d_in[13];
    const float* Ws2 = (const float*)d_in[14];
    const float* bs2 = (const float*)d_in[15];

    float* out_r = (float*)d_out;
    float* out_s = (float*)d_out + NB * NTF;

    float *gi, *fxg, *H;
    hf *Hhi, *Hlo, *xshi, *xslo, *seqhi, *seqlo, *xhi, *xlo, *fxhi, *fxlo, *sohi, *solo;
    hf *sbhi, *sblo, *abhi, *ablo;
    hf *hshi, *hslo, *hahi, *halo, *pshi, *pslo, *fahi, *falo;
    hf *Wsh, *Wah, *Wihh, *Whhh, *Ws2h;
    cudaGetSymbolAddress((void**)&gi, g_gi);     cudaGetSymbolAddress((void**)&fxg, g_fxg);
    cudaGetSymbolAddress((void**)&H, g_H);
    cudaGetSymbolAddress((void**)&Hhi, g_H_hi);  cudaGetSymbolAddress((void**)&Hlo, g_H_lo);
    cudaGetSymbolAddress((void**)&xshi, g_xs_hi); cudaGetSymbolAddress((void**)&xslo, g_xs_lo);
    cudaGetSymbolAddress((void**)&seqhi, g_seq_hi); cudaGetSymbolAddress((void**)&seqlo, g_seq_lo);
    cudaGetSymbolAddress((void**)&xhi, g_x_hi);  cudaGetSymbolAddress((void**)&xlo, g_x_lo);
    cudaGetSymbolAddress((void**)&fxhi, g_fx_hi); cudaGetSymbolAddress((void**)&fxlo, g_fx_lo);
    cudaGetSymbolAddress((void**)&sohi, g_so_hi); cudaGetSymbolAddress((void**)&solo, g_so_lo);
    cudaGetSymbolAddress((void**)&sbhi, g_sb_hi); cudaGetSymbolAddress((void**)&sblo, g_sb_lo);
    cudaGetSymbolAddress((void**)&abhi, g_ab_hi); cudaGetSymbolAddress((void**)&ablo, g_ab_lo);
    cudaGetSymbolAddress((void**)&hshi, g_hs_hi); cudaGetSymbolAddress((void**)&hslo, g_hs_lo);
    cudaGetSymbolAddress((void**)&hahi, g_ha_hi); cudaGetSymbolAddress((void**)&halo, g_ha_lo);
    cudaGetSymbolAddress((void**)&pshi, g_ps_hi); cudaGetSymbolAddress((void**)&pslo, g_ps_lo);
    cudaGetSymbolAddress((void**)&fahi, g_fa_hi); cudaGetSymbolAddress((void**)&falo, g_fa_lo);
    cudaGetSymbolAddress((void**)&Wsh, g_Ws_h);
    cudaGetSymbolAddress((void**)&Wah, g_Wa_h);
    cudaGetSymbolAddress((void**)&Wihh, g_Wih_h);
    cudaGetSymbolAddress((void**)&Whhh, g_Whh_h);
    cudaGetSymbolAddress((void**)&Ws2h, g_Ws2_h);

    cudaFuncSetAttribute(mma_gemm<128, 0>, cudaFuncAttributeMaxDynamicSharedMemorySize, SMEM128);
    cudaFuncSetAttribute(mma_gemm<128, 1>, cudaFuncAttributeMaxDynamicSharedMemorySize, SMEM128);
    cudaFuncSetAttribute(mma_gemm<64, 1>,  cudaFuncAttributeMaxDynamicSharedMemorySize, SMEM64);
    cudaFuncSetAttribute(mma_gemm<64, 3>,  cudaFuncAttributeMaxDynamicSharedMemorySize, SMEM64);
    cudaFuncSetAttribute(gru_step<0, 0>, cudaFuncAttributeMaxDynamicSharedMemorySize, SMS);
    cudaFuncSetAttribute(gru_step<0, 1>, cudaFuncAttributeMaxDynamicSharedMemorySize, SMS);
    cudaFuncSetAttribute(gru_step<1, 0>, cudaFuncAttributeMaxDynamicSharedMemorySize, SMD);

    auto sp2 = [&](const float* x, hf* hi, hf* lo, long n) {
        split2_k<<<(int)((n + 255) / 256), 256>>>(x, hi, lo, (int)n);
    };
    auto sp1 = [&](const float* x, hf* w, long n) {
        split1_k<<<(int)((n + 255) / 256), 256>>>(x, w, (int)n);
    };
    sp2(history_s, hshi, hslo, (long)NB * NTH * NS);
    sp2(history_a, hahi, halo, (long)NB * NTH * NA);
    sp2(present_s, pshi, pslo, (long)NB * NS);
    sp2(future_a,  fahi, falo, (long)NB * NTF * NA);
    sp1(Ws,  Wsh,  (long)NF * NS);
    sp1(Wa,  Wah,  (long)NF * NA);
    sp1(Wih, Wihh, (long)2 * NG * NF);
    sp1(Whh, Whhh, (long)2 * NG * NF);
    sp1(Ws2, Ws2h, (long)NS * NF);
    zeroH_k<<<(4 * NB * NF + 255) / 256, 256>>>(H, Hhi, Hlo, 4 * NB * NF);

    const hf *Wih0 = Wihh, *Wih1 = Wihh + (size_t)NG * NF;
    const hf *Whh0 = Whhh, *Whh1 = Whhh + (size_t)NG * NF;
    const float *bih0 = bih, *bih1 = bih + NG, *bhh0 = bhh, *bhh1 = bhh + NG;

    auto Hf  = [&](int l, int p) { return H   + (size_t)(l * 2 + p) * NB * NF; };
    auto Hfh = [&](int l, int p) { return Hhi + (size_t)(l * 2 + p) * NB * NF; };
    auto Hfl = [&](int l, int p) { return Hlo + (size_t)(l * 2 + p) * NB * NF; };
    int p0 = 0, p1 = 0;

    const dim3 GS(NF / 32, NB / 64);       // (32, 4) = 128 CTAs

    // embeddings (parallel)
    {   GP p = mkGP(hshi, hslo, NS, Wsh, bs, nullptr, 0, sbhi, sblo, NF);
        mma_gemm<128, 1><<<dim3(NF / 128, (NB * NTH) / 128), 128, SMEM128>>>(p, NS); }
    {   GP p = mkGP(hahi, halo, NA, Wah, ba, nullptr, 0, abhi, ablo, NF);
        mma_gemm<128, 1><<<dim3(NF / 128, (NB * NTH) / 128), 128, SMEM128>>>(p, NA); }
    {   GP p = mkGP(pshi, pslo, NS, Wsh, bs, nullptr, 0,
                    xshi + (size_t)64 * NB * NF, xslo + (size_t)64 * NB * NF, NF);
        mma_gemm<64, 1><<<dim3(NF / 64, NB / 128), 128, SMEM64>>>(p, NS); }
    {   GP p = mkGP(fahi, falo, NA, Wah, ba, nullptr, 0, fxhi, fxlo, NF);
        mma_gemm<128, 1><<<dim3(NF / 128, (NB * NTF) / 128), 128, SMEM128>>>(p, NA); }
    interleave_k<<<(64 * NB * NF / 2) / 256, 256>>>(sbhi, sblo, abhi, ablo, xshi, xslo);
    {   GP p = mkGP(fxhi, fxlo, NF, Wih0, nullptr, fxg, NG, nullptr, nullptr, 0);
        mma_gemm<128, 0><<<dim3(NG / 128, (NB * NTF) / 128), 128, SMEM128>>>(p, NF); }

    // layer 0 over prefix
    {   GP p = mkGP(xshi, xslo, NF, Wih0, nullptr, gi, NG, nullptr, nullptr, 0);
        mma_gemm<128, 0><<<dim3(NG / 128, (NT * NB) / 128), 128, SMEM128>>>(p, NF); }
    for (int t = 0; t < NT; t++) {
        gru_step<0, 1><<<GS, 128, SMS>>>(Hfh(0, p0), Hfl(0, p0), Whh0,
            nullptr, nullptr, nullptr,
            gi + (size_t)t * NB * NG, (long)NG, bih0, bhh0,
            Hf(0, p0), Hf(0, p0 ^ 1), Hfh(0, p0 ^ 1), Hfl(0, p0 ^ 1),
            seqhi + (size_t)t * NB * NF, seqlo + (size_t)t * NB * NF);
        p0 ^= 1;
    }
    // layer 1 over prefix
    {   GP p = mkGP(seqhi, seqlo, NF, Wih1, nullptr, gi, NG, nullptr, nullptr, 0);
        mma_gemm<128, 0><<<dim3(NG / 128, (NT * NB) / 128), 128, SMEM128>>>(p, NF); }
    for (int t = 0; t < NT; t++) {
        gru_step<0, 0><<<GS, 128, SMS>>>(Hfh(1, p1), Hfl(1, p1), Whh1,
            nullptr, nullptr, nullptr,
            gi + (size_t)t * NB * NG, (long)NG, bih1, bhh1,
            Hf(1, p1), Hf(1, p1 ^ 1), Hfh(1, p1 ^ 1), Hfl(1, p1 ^ 1),
            nullptr, nullptr);
        p1 ^= 1;
    }

    auto dcell = [&](const hf* Xh, const hf* Xl, int layer) {
        int& pp = layer ? p1 : p0;
        gru_step<1, 0><<<GS, 128, SMD>>>(
            Hfh(layer, pp), Hfl(layer, pp),
            layer ? Whh1 : Whh0,
            Xh, Xl, layer ? Wih1 : Wih0,
            nullptr, 0, layer ? bih1 : bih0, layer ? bhh1 : bhh0,
            Hf(layer, pp), Hf(layer, pp ^ 1), Hfh(layer, pp ^ 1), Hfl(layer, pp ^ 1),
            nullptr, nullptr);
        pp ^= 1;
    };

    // future rollout
    for (int i = 0; i < NTF; i++) {
        gru_step<0, 0><<<GS, 128, SMS>>>(Hfh(0, p0), Hfl(0, p0), Whh0,
            nullptr, nullptr, nullptr,
            fxg + (size_t)i * NG, (long)NTF * NG, bih0, bhh0,
            Hf(0, p0), Hf(0, p0 ^ 1), Hfh(0, p0 ^ 1), Hfl(0, p0 ^ 1),
            nullptr, nullptr);
        p0 ^= 1;
        dcell(Hfh(0, p0), Hfl(0, p0), 1);

        rproj_k<<<NB, 256>>>(Hf(1, p1), Wr, br, out_r, i);
        {   GP p = mkGP(Hfh(1, p1), Hfl(1, p1), NF, Ws2h, bs2,
                        out_s + (size_t)i * NS, (long)NTF * NS, sohi, solo, NS);
            mma_gemm<64, 3><<<dim3(NS / 64, NB / 128), 128, SMEM64>>>(p, NF); }
        {   GP p = mkGP(sohi, solo, NS, Wsh, bs, nullptr, 0, xhi, xlo, NF);
            mma_gemm<64, 1><<<dim3(NF / 64, NB / 128), 128, SMEM64>>>(p, NS); }
        dcell(xhi, xlo, 0);
        dcell(Hfh(0, p0), Hfl(0, p0), 1);
    }
}

// round 16
// speedup vs baseline: 1.5203x; 1.1167x over previous
#include <cuda_runtime.h>
#include <cuda_fp16.h>
#include <cstdint>
#include <math.h>

#define NB 256
#define NTH 32
#define NTF 16
#define NS 512
#define NA 128
#define NF 1024
#define NG 3072
#define NT 65

typedef __half hf;

// ------------------------------ scratch globals -------------------------------
__device__ float g_gi [(size_t)NT * NB * NG];
__device__ float g_fxg[(size_t)NB * NTF * NG];
__device__ float g_H  [4 * NB * NF];
__device__ hf g_H_hi[4 * NB * NF], g_H_lo[4 * NB * NF];
__device__ hf g_xs_hi [(size_t)NT * NB * NF], g_xs_lo [(size_t)NT * NB * NF];
__device__ hf g_seq_hi[(size_t)NT * NB * NF], g_seq_lo[(size_t)NT * NB * NF];
__device__ hf g_x_hi [NB * NF], g_x_lo [NB * NF];
__device__ hf g_fx_hi[NB * NTF * NF], g_fx_lo[NB * NTF * NF];
__device__ hf g_so_hi[NB * NS], g_so_lo[NB * NS];
__device__ hf g_sb_hi[NB * NTH * NF], g_sb_lo[NB * NTH * NF];
__device__ hf g_ab_hi[NB * NTH * NF], g_ab_lo[NB * NTH * NF];
__device__ hf g_hs_hi[NB * NTH * NS], g_hs_lo[NB * NTH * NS];
__device__ hf g_ha_hi[NB * NTH * NA], g_ha_lo[NB * NTH * NA];
__device__ hf g_ps_hi[NB * NS],       g_ps_lo[NB * NS];
__device__ hf g_fa_hi[NB * NTF * NA], g_fa_lo[NB * NTF * NA];
__device__ hf g_Ws_h [NF * NS];
__device__ hf g_Wa_h [NF * NA];
__device__ hf g_Wih_h[2 * NG * NF];
__device__ hf g_Whh_h[2 * NG * NF];
__device__ hf g_Ws2_h[NS * NF];

// ------------------------------- helpers --------------------------------------
__device__ __forceinline__ uint32_t smem_u32(const void* p) {
    uint32_t a;
    asm("{ .reg .u64 t; cvta.to.shared.u64 t, %1; cvt.u32.u64 %0, t; }" : "=r"(a) : "l"(p));
    return a;
}
#define CPA(d, s) asm volatile("cp.async.cg.shared.global [%0], [%1], 16;" :: "r"(d), "l"(s))
#define CPA_COMMIT() asm volatile("cp.async.commit_group;" ::: "memory")
#define CPA_WAIT1() asm volatile("cp.async.wait_group 1;" ::: "memory")
#define CPA_WAIT0() asm volatile("cp.async.wait_group 0;" ::: "memory")

#define LDSM4(r0, r1, r2, r3, a) \
    asm volatile("ldmatrix.sync.aligned.m8n8.x4.shared.b16 {%0,%1,%2,%3}, [%4];" \
                 : "=r"(r0), "=r"(r1), "=r"(r2), "=r"(r3) : "r"(a))
#define LDSM2(r0, r1, a) \
    asm volatile("ldmatrix.sync.aligned.m8n8.x2.shared.b16 {%0,%1}, [%2];" \
                 : "=r"(r0), "=r"(r1) : "r"(a))

__device__ __forceinline__ void mma4(float* d, const uint32_t* a, uint32_t b0, uint32_t b1) {
    asm volatile(
        "mma.sync.aligned.m16n8k16.row.col.f32.f16.f16.f32 "
        "{%0,%1,%2,%3},{%4,%5,%6,%7},{%8,%9},{%0,%1,%2,%3};"
        : "+f"(d[0]), "+f"(d[1]), "+f"(d[2]), "+f"(d[3])
        : "r"(a[0]), "r"(a[1]), "r"(a[2]), "r"(a[3]), "r"(b0), "r"(b1));
}

__device__ __forceinline__ void split2(float v, hf& h, hf& l) {
    h = __float2half_rn(v);
    l = __float2half_rn(v - __half2float(h));
}

// ------------------------- generic GEMM (parallel parts) -----------------------
struct GP {
    const hf *Ah, *Al, *W;
    const float* bias;
    float* C;
    hf *Ohi, *Olo;
    long lda, ldc, ldo;
};

// 128 threads / 4 warps.  Block 128 x BN.  Warp tile 64 x (BN/2).  ldmatrix frags.
// P = activation passes (1: A-hi only; 2: hi+lo).  Weight single fp16.
// MODE 0: fp32 C.  MODE 1: tanh(+bias)->hi/lo.  MODE 3: MODE1 + fp32 C.
template<int BN, int MODE, int P>
__global__ __launch_bounds__(128)
void mma_gemm(GP p, int K)
{
    extern __shared__ __align__(16) char sm[];
    constexpr int APL = 128 * 144;
    constexpr int BPL = BN * 144;
    constexpr int STAGE = P * APL + BPL;
    constexpr int WNT = BN / 16;
    constexpr int NPAIR = WNT / 2;

    const int tid = threadIdx.x, lane = tid & 31, warp = tid >> 5;
    const int wm = warp & 1, wn = warp >> 1;
    const int m0 = blockIdx.y * 128, n0 = blockIdx.x * BN;
    const uint32_t sb = smem_u32(sm);
    const int lq = lane >> 2, lr = lane & 3;
    const int r8 = lane & 7;

    float acc[4][WNT][4];
    #pragma unroll
    for (int i = 0; i < 4; i++)
        #pragma unroll
        for (int j = 0; j < WNT; j++)
            #pragma unroll
            for (int q = 0; q < 4; q++) acc[i][j][q] = 0.f;

    auto load_stage = [&](int s, int k0) {
        uint32_t ab = sb + s * STAGE;
        #pragma unroll
        for (int v = tid; v < 1024; v += 128) {
            int row = v >> 3, q = v & 7;
            size_t g = (size_t)(m0 + row) * p.lda + k0 + q * 8;
            uint32_t d = ab + row * 144 + q * 16;
            CPA(d, p.Ah + g);
            if (P == 2) CPA(d + APL, p.Al + g);
        }
        #pragma unroll
        for (int v = tid; v < BN * 8; v += 128) {
            int row = v >> 3, q = v & 7;
            size_t g = (size_t)(n0 + row) * K + k0 + q * 8;
            CPA(ab + P * APL + row * 144 + q * 16, p.W + g);
        }
    };

    const int NC = K >> 6;
    load_stage(0, 0);
    CPA_COMMIT();

    for (int c = 0; c < NC; c++) {
        if (c + 1 < NC) { load_stage((c + 1) & 1, (c + 1) << 6); CPA_COMMIT(); CPA_WAIT1(); }
        else           { CPA_WAIT0(); }
        __syncthreads();

        const int s = c & 1;
        uint32_t aH = sb + s * STAGE, aL = aH + APL, bW = sb + s * STAGE + P * APL;
        #pragma unroll
        for (int kk = 0; kk < 4; kk++) {
            const uint32_t aRow = (uint32_t)(wm * 64 + ((lane >> 3) & 1) * 8 + r8);
            const uint32_t aCol = (uint32_t)(kk * 32 + ((lane >> 4) & 1) * 16);
            uint32_t ah[4][4], al[4][4];
            #pragma unroll
            for (int mt = 0; mt < 4; mt++) {
                uint32_t ad = (aRow + mt * 16) * 144 + aCol;
                LDSM4(ah[mt][0], ah[mt][1], ah[mt][2], ah[mt][3], aH + ad);
                if (P == 2) LDSM4(al[mt][0], al[mt][1], al[mt][2], al[mt][3], aL + ad);
            }
            uint32_t bh[NPAIR][4];
            const uint32_t bCol = (uint32_t)(kk * 32 + ((lane >> 3) & 1) * 16);
            #pragma unroll
            for (int np = 0; np < NPAIR; np++) {
                uint32_t bRow = (uint32_t)(wn * (BN / 2) + np * 16 + ((lane >> 4) & 1) * 8 + r8);
                LDSM4(bh[np][0], bh[np][1], bh[np][2], bh[np][3], bW + bRow * 144 + bCol);
            }
            #pragma unroll
            for (int np = 0; np < NPAIR; np++) {
                #pragma unroll
                for (int sd = 0; sd < 2; sd++) {
                    int nt = np * 2 + sd;
                    #pragma unroll
                    for (int mt = 0; mt < 4; mt++) {
                        mma4(acc[mt][nt], ah[mt], bh[np][sd * 2], bh[np][sd * 2 + 1]);
                        if (P == 2)
                            mma4(acc[mt][nt], al[mt], bh[np][sd * 2], bh[np][sd * 2 + 1]);
                    }
                }
            }
        }
        __syncthreads();
    }

    #pragma unroll
    for (int mt = 0; mt < 4; mt++) {
        #pragma unroll
        for (int nt = 0; nt < WNT; nt++) {
            int gm = m0 + wm * 64 + mt * 16 + lq;
            int gn = n0 + wn * (BN / 2) + nt * 8 + lr * 2;
            float* a = acc[mt][nt];
            if (MODE == 0) {
                float2 v0; v0.x = a[0]; v0.y = a[1];
                float2 v1; v1.x = a[2]; v1.y = a[3];
                *reinterpret_cast<float2*>(p.C + (size_t)gm * p.ldc + gn) = v0;
                *reinterpret_cast<float2*>(p.C + (size_t)(gm + 8) * p.ldc + gn) = v1;
            } else {
                float b0 = p.bias[gn], b1 = p.bias[gn + 1];
                float v00 = tanhf(a[0] + b0), v01 = tanhf(a[1] + b1);
                float v10 = tanhf(a[2] + b0), v11 = tanhf(a[3] + b1);
                __half2 h0, l0, h1, l1;
                split2(v00, h0.x, l0.x); split2(v01, h0.y, l0.y);
                split2(v10, h1.x, l1.x); split2(v11, h1.y, l1.y);
                *reinterpret_cast<__half2*>(p.Ohi + (size_t)gm * p.ldo + gn) = h0;
                *reinterpret_cast<__half2*>(p.Olo + (size_t)gm * p.ldo + gn) = l0;
                *reinterpret_cast<__half2*>(p.Ohi + (size_t)(gm + 8) * p.ldo + gn) = h1;
                *reinterpret_cast<__half2*>(p.Olo + (size_t)(gm + 8) * p.ldo + gn) = l1;
                if (MODE == 3) {
                    float2 v0; v0.x = v00; v0.y = v01;
                    float2 v1; v1.x = v10; v1.y = v11;
                    *reinterpret_cast<float2*>(p.C + (size_t)gm * p.ldc + gn) = v0;
                    *reinterpret_cast<float2*>(p.C + (size_t)(gm + 8) * p.ldc + gn) = v1;
                }
            }
        }
    }
}

// ------------------- fused GRU step: gh GEMM (+gi GEMM) + gates ----------------
// 128 threads / 4 warps.  Block tile: 64 batch rows x (32 f x 3 gates = 96).
// Activations 2-pass (recurrent path keeps hi/lo), weights single fp16.
__device__ __forceinline__ void gs_compute(uint32_t aH, uint32_t aL, uint32_t bW,
                                           int wn, int lane, int kk, float (*acc)[3][4])
{
    const int r8 = lane & 7;
    const uint32_t aRow = (uint32_t)(((lane >> 3) & 1) * 8 + r8);
    const uint32_t aCol = (uint32_t)(kk * 32 + ((lane >> 4) & 1) * 16);
    uint32_t ah[4][4], al[4][4];
    #pragma unroll
    for (int mt = 0; mt < 4; mt++) {
        uint32_t ad = (aRow + mt * 16) * 144 + aCol;
        LDSM4(ah[mt][0], ah[mt][1], ah[mt][2], ah[mt][3], aH + ad);
        LDSM4(al[mt][0], al[mt][1], al[mt][2], al[mt][3], aL + ad);
    }
    uint32_t bh[6];
    const uint32_t bCol = (uint32_t)(kk * 32 + ((lane >> 3) & 1) * 16);
    {
        uint32_t bRow = (uint32_t)(wn * 24 + ((lane >> 4) & 1) * 8 + r8);
        LDSM4(bh[0], bh[1], bh[2], bh[3], bW + bRow * 144 + bCol);
    }
    {
        uint32_t bRow = (uint32_t)(wn * 24 + 16 + r8);
        LDSM2(bh[4], bh[5], bW + bRow * 144 + bCol);
    }
    #pragma unroll
    for (int nt = 0; nt < 3; nt++) {
        uint32_t b0 = bh[nt * 2], b1 = bh[nt * 2 + 1];
        #pragma unroll
        for (int mt = 0; mt < 4; mt++) {
            mma4(acc[mt][nt], ah[mt], b0, b1);
            mma4(acc[mt][nt], al[mt], b0, b1);
        }
    }
}

template<int DUAL, int WSEQ>
__global__ __launch_bounds__(128)
void gru_step(const hf* __restrict__ Hh, const hf* __restrict__ Hl,
              const hf* __restrict__ Wh,
              const hf* __restrict__ Xh, const hf* __restrict__ Xl,
              const hf* __restrict__ Wi,
              const float* __restrict__ giB, long giS,
              const float* __restrict__ bih, const float* __restrict__ bhh,
              const float* __restrict__ hOld,
              float* __restrict__ hNew, hf* __restrict__ nhi, hf* __restrict__ nlo,
              hf* __restrict__ shi, hf* __restrict__ slo)
{
    extern __shared__ __align__(16) char sm[];
    constexpr int APL = 64 * 144, BPL = 96 * 144;
    constexpr int NPA = DUAL ? 4 : 2;
    constexpr int NPB = DUAL ? 2 : 1;
    constexpr int STAGE = NPA * APL + NPB * BPL;

    const int tid = threadIdx.x, lane = tid & 31, wn = tid >> 5;
    const int lq = lane >> 2, lr = lane & 3;
    const int f0 = blockIdx.x * 32, m0 = blockIdx.y * 64;
    const uint32_t sb = smem_u32(sm);

    float acch[4][3][4];
    float acci[4][3][4];
    #pragma unroll
    for (int i = 0; i < 4; i++)
        #pragma unroll
        for (int j = 0; j < 3; j++)
            #pragma unroll
            for (int q = 0; q < 4; q++) { acch[i][j][q] = 0.f; acci[i][j][q] = 0.f; }

    auto load_stage = [&](int s, int k0) {
        uint32_t base = sb + s * STAGE;
        #pragma unroll
        for (int v = tid; v < 512; v += 128) {
            int row = v >> 3, q = v & 7;
            size_t g = (size_t)(m0 + row) * NF + k0 + q * 8;
            uint32_t d = base + row * 144 + q * 16;
            CPA(d, Hh + g);
            CPA(d + APL, Hl + g);
            if (DUAL) { CPA(d + 2 * APL, Xh + g); CPA(d + 3 * APL, Xl + g); }
        }
        uint32_t bb = base + NPA * APL;
        #pragma unroll
        for (int v = tid; v < 768; v += 128) {
            int rr = v >> 3, q8 = v & 7;
            int qq = rr / 24, rem = rr - qq * 24;
            int g = rem >> 3, u = rem & 7;
            size_t R = (size_t)(g * 1024 + f0 + qq * 8 + u) * NF + k0 + q8 * 8;
            uint32_t d = bb + rr * 144 + q8 * 16;
            CPA(d, Wh + R);
            if (DUAL) CPA(d + BPL, Wi + R);
        }
    };

    const int NC = NF >> 6;          // 16
    load_stage(0, 0);
    CPA_COMMIT();

    for (int c = 0; c < NC; c++) {
        if (c + 1 < NC) { load_stage((c + 1) & 1, (c + 1) << 6); CPA_COMMIT(); CPA_WAIT1(); }
        else           { CPA_WAIT0(); }
        __syncthreads();

        uint32_t base = sb + (c & 1) * STAGE;
        uint32_t bb = base + NPA * APL;
        #pragma unroll
        for (int kk = 0; kk < 4; kk++) {
            gs_compute(base, base + APL, bb, wn, lane, kk, acch);
            if (DUAL)
                gs_compute(base + 2 * APL, base + 3 * APL, bb + BPL, wn, lane, kk, acci);
        }
        __syncthreads();
    }

    // ---- fused GRU gate epilogue ----
    const int fc = f0 + wn * 8 + lr * 2;
    float bi[3][2], bh_[3][2];
    #pragma unroll
    for (int g = 0; g < 3; g++) {
        bi[g][0]  = bih[g * 1024 + fc];  bi[g][1]  = bih[g * 1024 + fc + 1];
        bh_[g][0] = bhh[g * 1024 + fc];  bh_[g][1] = bhh[g * 1024 + fc + 1];
    }
    #pragma unroll
    for (int mt = 0; mt < 4; mt++) {
        #pragma unroll
        for (int half = 0; half < 2; half++) {
            int b = m0 + mt * 16 + lq + half * 8;
            float o[2];
            #pragma unroll
            for (int cidx = 0; cidx < 2; cidx++) {
                int k = half * 2 + cidx;
                int f = fc + cidx;
                float hr = acch[mt][0][k], hz = acch[mt][1][k], hn = acch[mt][2][k];
                float ir, iz, in_;
                if (DUAL) {
                    ir = acci[mt][0][k]; iz = acci[mt][1][k]; in_ = acci[mt][2][k];
                } else {
                    const float* gp = giB + (size_t)b * giS;
                    ir = gp[f]; iz = gp[1024 + f]; in_ = gp[2048 + f];
                }
                float r = 1.f / (1.f + expf(-(ir + bi[0][cidx] + hr + bh_[0][cidx])));
                float z = 1.f / (1.f + expf(-(iz + bi[1][cidx] + hz + bh_[1][cidx])));
                float n = tanhf(in_ + bi[2][cidx] + r * (hn + bh_[2][cidx]));
                float ho = hOld[(size_t)b * NF + f];
                o[cidx] = (1.f - z) * n + z * ho;
            }
            float2 o2; o2.x = o[0]; o2.y = o[1];
            *reinterpret_cast<float2*>(hNew + (size_t)b * NF + fc) = o2;
            __half2 hh, ll;
            split2(o[0], hh.x, ll.x);
            split2(o[1], hh.y, ll.y);
            *reinterpret_cast<__half2*>(nhi + (size_t)b * NF + fc) = hh;
            *reinterpret_cast<__half2*>(nlo + (size_t)b * NF + fc) = ll;
            if (WSEQ) {
                *reinterpret_cast<__half2*>(shi + (size_t)b * NF + fc) = hh;
                *reinterpret_cast<__half2*>(slo + (size_t)b * NF + fc) = ll;
            }
        }
    }
}

// ------------------------------ small kernels ----------------------------------
__global__ void interleave_k(const hf* __restrict__ sh, const hf* __restrict__ sl,
                             const hf* __restrict__ ah, const hf* __restrict__ al,
                             hf* __restrict__ xh, hf* __restrict__ xl)
{
    int i = blockIdx.x * blockDim.x + threadIdx.x;
    int t = i / (NB * NF / 2);
    int rem = i % (NB * NF / 2);
    int b = rem / (NF / 2), f2 = rem % (NF / 2);
    int u = t >> 1;
    size_t src = (size_t)(b * NTH + u) * (NF / 2) + f2;
    const uint32_t* ph = reinterpret_cast<const uint32_t*>((t & 1) ? ah : sh);
    const uint32_t* pl = reinterpret_cast<const uint32_t*>((t & 1) ? al : sl);
    reinterpret_cast<uint32_t*>(xh)[i] = ph[src];
    reinterpret_cast<uint32_t*>(xl)[i] = pl[src];
}

__global__ void rproj_k(const float* __restrict__ H1, const float* __restrict__ Wr,
                        const float* __restrict__ br, float* __restrict__ out_r, int step)
{
    __shared__ float red[256];
    int b = blockIdx.x;
    float p = 0.f;
    for (int k = threadIdx.x; k < NF; k += 256) p += H1[(size_t)b * NF + k] * Wr[k];
    red[threadIdx.x] = p;
    __syncthreads();
    for (int s = 128; s > 0; s >>= 1) {
        if (threadIdx.x < s) red[threadIdx.x] += red[threadIdx.x + s];
        __syncthreads();
    }
    if (threadIdx.x == 0)
        out_r[b * NTF + step] = 1.f / (1.f + expf(-(red[0] + br[0])));
}

__global__ void split2_k(const float* __restrict__ x, hf* __restrict__ hi,
                         hf* __restrict__ lo, int n)
{
    int i = blockIdx.x * blockDim.x + threadIdx.x;
    if (i < n) {
        hf h, l;
        split2(x[i], h, l);
        hi[i] = h; lo[i] = l;
    }
}

__global__ void split1_k(const float* __restrict__ x, hf* __restrict__ w, int n)
{
    int i = blockIdx.x * blockDim.x + threadIdx.x;
    if (i < n) w[i] = __float2half_rn(x[i]);
}

__global__ void zeroH_k(float* h, hf* hi, hf* lo, int n)
{
    int i = blockIdx.x * blockDim.x + threadIdx.x;
    if (i < n) { h[i] = 0.f; hi[i] = __float2half_rn(0.f); lo[i] = __float2half_rn(0.f); }
}

// ----------------------------------- host --------------------------------------
static const int SM128P1 = 2 * (128 * 144 + 128 * 144);       // 73728
static const int SM64P1  = 2 * (128 * 144 +  64 * 144);       // 55296
static const int SMS     = 2 * (2 * 64 * 144 + 96 * 144);     // 64512
static const int SMD     = 2 * (4 * 64 * 144 + 2 * 96 * 144); // 129024

static inline GP mkGP(const hf* Ah, const hf* Al, long lda, const hf* W,
                      const float* bias, float* C, long ldc,
                      hf* Ohi, hf* Olo, long ldo)
{
    GP p; p.Ah = Ah; p.Al = Al; p.W = W; p.bias = bias;
    p.C = C; p.Ohi = Ohi; p.Olo = Olo; p.lda = lda; p.ldc = ldc; p.ldo = ldo;
    return p;
}

extern "C" void kernel_launch(void* const* d_in, const int* in_sizes, int n_in,
                              void* d_out, int out_size)
{
    (void)in_sizes; (void)n_in; (void)out_size;
    const float* history_s = (const float*)d_in[0];
    const float* history_a = (const float*)d_in[1];
    const float* present_s = (const float*)d_in[2];
    const float* future_a  = (const float*)d_in[3];
    const float* Ws  = (const float*)d_in[4];
    const float* bs  = (const float*)d_in[5];
    const float* Wa  = (const float*)d_in[6];
    const float* ba  = (const float*)d_in[7];
    const float* Wih = (const float*)d_in[8];
    const float* Whh = (const float*)d_in[9];
    const float* bih = (const float*)d_in[10];
    const float* bhh = (const float*)d_in[11];
    const float* Wr  = (const float*)d_in[12];
    const float* br  = (const float*)d_in[13];
    const float* Ws2 = (const float*)d_in[14];
    const float* bs2 = (const float*)d_in[15];

    float* out_r = (float*)d_out;
    float* out_s = (float*)d_out + NB * NTF;

    float *gi, *fxg, *H;
    hf *Hhi, *Hlo, *xshi, *xslo, *seqhi, *seqlo, *xhi, *xlo, *fxhi, *fxlo, *sohi, *solo;
    hf *sbhi, *sblo, *abhi, *ablo;
    hf *hshi, *hslo, *hahi, *halo, *pshi, *pslo, *fahi, *falo;
    hf *Wsh, *Wah, *Wihh, *Whhh, *Ws2h;
    cudaGetSymbolAddress((void**)&gi, g_gi);     cudaGetSymbolAddress((void**)&fxg, g_fxg);
    cudaGetSymbolAddress((void**)&H, g_H);
    cudaGetSymbolAddress((void**)&Hhi, g_H_hi);  cudaGetSymbolAddress((void**)&Hlo, g_H_lo);
    cudaGetSymbolAddress((void**)&xshi, g_xs_hi); cudaGetSymbolAddress((void**)&xslo, g_xs_lo);
    cudaGetSymbolAddress((void**)&seqhi, g_seq_hi); cudaGetSymbolAddress((void**)&seqlo, g_seq_lo);
    cudaGetSymbolAddress((void**)&xhi, g_x_hi);  cudaGetSymbolAddress((void**)&xlo, g_x_lo);
    cudaGetSymbolAddress((void**)&fxhi, g_fx_hi); cudaGetSymbolAddress((void**)&fxlo, g_fx_lo);
    cudaGetSymbolAddress((void**)&sohi, g_so_hi); cudaGetSymbolAddress((void**)&solo, g_so_lo);
    cudaGetSymbolAddress((void**)&sbhi, g_sb_hi); cudaGetSymbolAddress((void**)&sblo, g_sb_lo);
    cudaGetSymbolAddress((void**)&abhi, g_ab_hi); cudaGetSymbolAddress((void**)&ablo, g_ab_lo);
    cudaGetSymbolAddress((void**)&hshi, g_hs_hi); cudaGetSymbolAddress((void**)&hslo, g_hs_lo);
    cudaGetSymbolAddress((void**)&hahi, g_ha_hi); cudaGetSymbolAddress((void**)&halo, g_ha_lo);
    cudaGetSymbolAddress((void**)&pshi, g_ps_hi); cudaGetSymbolAddress((void**)&pslo, g_ps_lo);
    cudaGetSymbolAddress((void**)&fahi, g_fa_hi); cudaGetSymbolAddress((void**)&falo, g_fa_lo);
    cudaGetSymbolAddress((void**)&Wsh, g_Ws_h);
    cudaGetSymbolAddress((void**)&Wah, g_Wa_h);
    cudaGetSymbolAddress((void**)&Wihh, g_Wih_h);
    cudaGetSymbolAddress((void**)&Whhh, g_Whh_h);
    cudaGetSymbolAddress((void**)&Ws2h, g_Ws2_h);

    cudaFuncSetAttribute(mma_gemm<128, 0, 1>, cudaFuncAttributeMaxDynamicSharedMemorySize, SM128P1);
    cudaFuncSetAttribute(mma_gemm<128, 1, 1>, cudaFuncAttributeMaxDynamicSharedMemorySize, SM128P1);
    cudaFuncSetAttribute(mma_gemm<64, 1, 1>,  cudaFuncAttributeMaxDynamicSharedMemorySize, SM64P1);
    cudaFuncSetAttribute(mma_gemm<64, 3, 1>,  cudaFuncAttributeMaxDynamicSharedMemorySize, SM64P1);
    cudaFuncSetAttribute(gru_step<0, 0>, cudaFuncAttributeMaxDynamicSharedMemorySize, SMS);
    cudaFuncSetAttribute(gru_step<0, 1>, cudaFuncAttributeMaxDynamicSharedMemorySize, SMS);
    cudaFuncSetAttribute(gru_step<1, 0>, cudaFuncAttributeMaxDynamicSharedMemorySize, SMD);

    auto sp2 = [&](const float* x, hf* hi, hf* lo, long n) {
        split2_k<<<(int)((n + 255) / 256), 256>>>(x, hi, lo, (int)n);
    };
    auto sp1 = [&](const float* x, hf* w, long n) {
        split1_k<<<(int)((n + 255) / 256), 256>>>(x, w, (int)n);
    };
    sp2(history_s, hshi, hslo, (long)NB * NTH * NS);
    sp2(history_a, hahi, halo, (long)NB * NTH * NA);
    sp2(present_s, pshi, pslo, (long)NB * NS);
    sp2(future_a,  fahi, falo, (long)NB * NTF * NA);
    sp1(Ws,  Wsh,  (long)NF * NS);
    sp1(Wa,  Wah,  (long)NF * NA);
    sp1(Wih, Wihh, (long)2 * NG * NF);
    sp1(Whh, Whhh, (long)2 * NG * NF);
    sp1(Ws2, Ws2h, (long)NS * NF);
    zeroH_k<<<(4 * NB * NF + 255) / 256, 256>>>(H, Hhi, Hlo, 4 * NB * NF);

    const hf *Wih0 = Wihh, *Wih1 = Wihh + (size_t)NG * NF;
    const hf *Whh0 = Whhh, *Whh1 = Whhh + (size_t)NG * NF;
    const float *bih0 = bih, *bih1 = bih + NG, *bhh0 = bhh, *bhh1 = bhh + NG;

    auto Hf  = [&](int l, int p) { return H   + (size_t)(l * 2 + p) * NB * NF; };
    auto Hfh = [&](int l, int p) { return Hhi + (size_t)(l * 2 + p) * NB * NF; };
    auto Hfl = [&](int l, int p) { return Hlo + (size_t)(l * 2 + p) * NB * NF; };
    int p0 = 0, p1 = 0;

    const dim3 GS(NF / 32, NB / 64);       // (32, 4) = 128 CTAs

    // embeddings (parallel, 1-pass)
    {   GP p = mkGP(hshi, hslo, NS, Wsh, bs, nullptr, 0, sbhi, sblo, NF);
        mma_gemm<128, 1, 1><<<dim3(NF / 128, (NB * NTH) / 128), 128, SM128P1>>>(p, NS); }
    {   GP p = mkGP(hahi, halo, NA, Wah, ba, nullptr, 0, abhi, ablo, NF);
        mma_gemm<128, 1, 1><<<dim3(NF / 128, (NB * NTH) / 128), 128, SM128P1>>>(p, NA); }
    {   GP p = mkGP(pshi, pslo, NS, Wsh, bs, nullptr, 0,
                    xshi + (size_t)64 * NB * NF, xslo + (size_t)64 * NB * NF, NF);
        mma_gemm<64, 1, 1><<<dim3(NF / 64, NB / 128), 128, SM64P1>>>(p, NS); }
    {   GP p = mkGP(fahi, falo, NA, Wah, ba, nullptr, 0, fxhi, fxlo, NF);
        mma_gemm<128, 1, 1><<<dim3(NF / 128, (NB * NTF) / 128), 128, SM128P1>>>(p, NA); }
    interleave_k<<<(64 * NB * NF / 2) / 256, 256>>>(sbhi, sblo, abhi, ablo, xshi, xslo);
    {   GP p = mkGP(fxhi, fxlo, NF, Wih0, nullptr, fxg, NG, nullptr, nullptr, 0);
        mma_gemm<128, 0, 1><<<dim3(NG / 128, (NB * NTF) / 128), 128, SM128P1>>>(p, NF); }

    // layer 0 over prefix
    {   GP p = mkGP(xshi, xslo, NF, Wih0, nullptr, gi, NG, nullptr, nullptr, 0);
        mma_gemm<128, 0, 1><<<dim3(NG / 128, (NT * NB) / 128), 128, SM128P1>>>(p, NF); }
    for (int t = 0; t < NT; t++) {
        gru_step<0, 1><<<GS, 128, SMS>>>(Hfh(0, p0), Hfl(0, p0), Whh0,
            nullptr, nullptr, nullptr,
            gi + (size_t)t * NB * NG, (long)NG, bih0, bhh0,
            Hf(0, p0), Hf(0, p0 ^ 1), Hfh(0, p0 ^ 1), Hfl(0, p0 ^ 1),
            seqhi + (size_t)t * NB * NF, seqlo + (size_t)t * NB * NF);
        p0 ^= 1;
    }
    // layer 1 over prefix
    {   GP p = mkGP(seqhi, seqlo, NF, Wih1, nullptr, gi, NG, nullptr, nullptr, 0);
        mma_gemm<128, 0, 1><<<dim3(NG / 128, (NT * NB) / 128), 128, SM128P1>>>(p, NF); }
    for (int t = 0; t < NT; t++) {
        gru_step<0, 0><<<GS, 128, SMS>>>(Hfh(1, p1), Hfl(1, p1), Whh1,
            nullptr, nullptr, nullptr,
            gi + (size_t)t * NB * NG, (long)NG, bih1, bhh1,
            Hf(1, p1), Hf(1, p1 ^ 1), Hfh(1, p1 ^ 1), Hfl(1, p1 ^ 1),
            nullptr, nullptr);
        p1 ^= 1;
    }

    auto dcell = [&](const hf* Xh, const hf* Xl, int layer) {
        int& pp = layer ? p1 : p0;
        gru_step<1, 0><<<GS, 128, SMD>>>(
            Hfh(layer, pp), Hfl(layer, pp),
            layer ? Whh1 : Whh0,
            Xh, Xl, layer ? Wih1 : Wih0,
            nullptr, 0, layer ? bih1 : bih0, layer ? bhh1 : bhh0,
            Hf(layer, pp), Hf(layer, pp ^ 1), Hfh(layer, pp ^ 1), Hfl(layer, pp ^ 1),
            nullptr, nullptr);
        pp ^= 1;
    };

    // future rollout
    for (int i = 0; i < NTF; i++) {
        gru_step<0, 0><<<GS, 128, SMS>>>(Hfh(0, p0), Hfl(0, p0), Whh0,
            nullptr, nullptr, nullptr,
            fxg + (size_t)i * NG, (long)NTF * NG, bih0, bhh0,
            Hf(0, p0), Hf(0, p0 ^ 1), Hfh(0, p0 ^ 1), Hfl(0, p0 ^ 1),
            nullptr, nullptr);
        p0 ^= 1;
        dcell(Hfh(0, p0), Hfl(0, p0), 1);

        rproj_k<<<NB, 256>>>(Hf(1, p1), Wr, br, out_r, i);
        {   GP p = mkGP(Hfh(1, p1), Hfl(1, p1), NF, Ws2h, bs2,
                        out_s + (size_t)i * NS, (long)NTF * NS, sohi, solo, NS);
            mma_gemm<64, 3, 1><<<dim3(NS / 64, NB / 128), 128, SM64P1>>>(p, NF); }
        {   GP p = mkGP(sohi, solo, NS, Wsh, bs, nullptr, 0, xhi, xlo, NF);
            mma_gemm<64, 1, 1><<<dim3(NF / 64, NB / 128), 128, SM64P1>>>(p, NS); }
        dcell(xhi, xlo, 0);
        dcell(Hfh(0, p0), Hfl(0, p0), 1);
    }
}

// round 17
// speedup vs baseline: 1.5446x; 1.0160x over previous
#include <cuda_runtime.h>
#include <cuda_fp16.h>
#include <cstdint>
#include <math.h>

#define NB 256
#define NTH 32
#define NTF 16
#define NS 512
#define NA 128
#define NF 1024
#define NG 3072
#define NT 65

typedef __half hf;

// ------------------------------ scratch globals -------------------------------
__device__ float g_gi [(size_t)NT * NB * NG];
__device__ float g_fxg[(size_t)NB * NTF * NG];
__device__ float g_H  [4 * NB * NF];
__device__ hf g_H_hi[4 * NB * NF], g_H_lo[4 * NB * NF];
__device__ hf g_xs_hi [(size_t)NT * NB * NF], g_xs_lo [(size_t)NT * NB * NF];
__device__ hf g_seq_hi[(size_t)NT * NB * NF], g_seq_lo[(size_t)NT * NB * NF];
__device__ hf g_x_hi [NB * NF], g_x_lo [NB * NF];
__device__ hf g_fx_hi[NB * NTF * NF], g_fx_lo[NB * NTF * NF];
__device__ hf g_so_hi[NB * NS], g_so_lo[NB * NS];
__device__ hf g_hs_hi[NB * NTH * NS], g_hs_lo[NB * NTH * NS];
__device__ hf g_ha_hi[NB * NTH * NA], g_ha_lo[NB * NTH * NA];
__device__ hf g_ps_hi[NB * NS],       g_ps_lo[NB * NS];
__device__ hf g_fa_hi[NB * NTF * NA], g_fa_lo[NB * NTF * NA];
__device__ hf g_Ws_h [NF * NS];
__device__ hf g_Wa_h [NF * NA];
__device__ hf g_Wih_h[2 * NG * NF];
__device__ hf g_Whh_h[2 * NG * NF];
__device__ hf g_Ws2_h[NS * NF];

// ------------------------------- helpers --------------------------------------
__device__ __forceinline__ uint32_t smem_u32(const void* p) {
    uint32_t a;
    asm("{ .reg .u64 t; cvta.to.shared.u64 t, %1; cvt.u32.u64 %0, t; }" : "=r"(a) : "l"(p));
    return a;
}
#define CPA(d, s) asm volatile("cp.async.cg.shared.global [%0], [%1], 16;" :: "r"(d), "l"(s))
#define CPA_COMMIT() asm volatile("cp.async.commit_group;" ::: "memory")
#define CPA_WAIT1() asm volatile("cp.async.wait_group 1;" ::: "memory")
#define CPA_WAIT0() asm volatile("cp.async.wait_group 0;" ::: "memory")

#define LDSM4(r0, r1, r2, r3, a) \
    asm volatile("ldmatrix.sync.aligned.m8n8.x4.shared.b16 {%0,%1,%2,%3}, [%4];" \
                 : "=r"(r0), "=r"(r1), "=r"(r2), "=r"(r3) : "r"(a))
#define LDSM2(r0, r1, a) \
    asm volatile("ldmatrix.sync.aligned.m8n8.x2.shared.b16 {%0,%1}, [%2];" \
                 : "=r"(r0), "=r"(r1) : "r"(a))

__device__ __forceinline__ void mma4(float* d, const uint32_t* a, uint32_t b0, uint32_t b1) {
    asm volatile(
        "mma.sync.aligned.m16n8k16.row.col.f32.f16.f16.f32 "
        "{%0,%1,%2,%3},{%4,%5,%6,%7},{%8,%9},{%0,%1,%2,%3};"
        : "+f"(d[0]), "+f"(d[1]), "+f"(d[2]), "+f"(d[3])
        : "r"(a[0]), "r"(a[1]), "r"(a[2]), "r"(a[3]), "r"(b0), "r"(b1));
}

__device__ __forceinline__ void split2(float v, hf& h, hf& l) {
    h = __float2half_rn(v);
    l = __float2half_rn(v - __half2float(h));
}

// ------------------------- generic GEMM (parallel parts) -----------------------
struct GP {
    const hf *Ah, *Al, *W;
    const float* bias;
    float* C;
    hf *Ohi, *Olo;
    long lda, ldc, ldo;
    long K;
    int par;
};

// 128 threads / 4 warps.  Block 128 x BN.  Warp tile 64 x (BN/2).  ldmatrix frags.
// P = activation passes (1: A-hi only; 2: hi+lo).  Weight single fp16.
// MODE 0: fp32 C.  MODE 1: tanh(+bias)->hi/lo.  MODE 2: MODE1 + prefix scatter
// (A row b*32+u -> out row (2u+par)*NB + b).  MODE 3: MODE1 + fp32 C.
// blockIdx.z picks p0/p1 (dual GEMM; K per GP).
template<int BN, int MODE, int P>
__global__ __launch_bounds__(128)
void mma_gemm(GP p0, GP p1)
{
    const GP p = (blockIdx.z == 0) ? p0 : p1;
    const int K = (int)p.K;
    extern __shared__ __align__(16) char sm[];
    constexpr int APL = 128 * 144;
    constexpr int BPL = BN * 144;
    constexpr int STAGE = P * APL + BPL;
    constexpr int WNT = BN / 16;
    constexpr int NPAIR = WNT / 2;

    const int tid = threadIdx.x, lane = tid & 31, warp = tid >> 5;
    const int wm = warp & 1, wn = warp >> 1;
    const int m0 = blockIdx.y * 128, n0 = blockIdx.x * BN;
    const uint32_t sb = smem_u32(sm);
    const int lq = lane >> 2, lr = lane & 3;
    const int r8 = lane & 7;

    float acc[4][WNT][4];
    #pragma unroll
    for (int i = 0; i < 4; i++)
        #pragma unroll
        for (int j = 0; j < WNT; j++)
            #pragma unroll
            for (int q = 0; q < 4; q++) acc[i][j][q] = 0.f;

    auto load_stage = [&](int s, int k0) {
        uint32_t ab = sb + s * STAGE;
        #pragma unroll
        for (int v = tid; v < 1024; v += 128) {
            int row = v >> 3, q = v & 7;
            size_t g = (size_t)(m0 + row) * p.lda + k0 + q * 8;
            uint32_t d = ab + row * 144 + q * 16;
            CPA(d, p.Ah + g);
            if (P == 2) CPA(d + APL, p.Al + g);
        }
        #pragma unroll
        for (int v = tid; v < BN * 8; v += 128) {
            int row = v >> 3, q = v & 7;
            size_t g = (size_t)(n0 + row) * K + k0 + q * 8;
            CPA(ab + P * APL + row * 144 + q * 16, p.W + g);
        }
    };

    const int NC = K >> 6;
    load_stage(0, 0);
    CPA_COMMIT();

    for (int c = 0; c < NC; c++) {
        if (c + 1 < NC) { load_stage((c + 1) & 1, (c + 1) << 6); CPA_COMMIT(); CPA_WAIT1(); }
        else           { CPA_WAIT0(); }
        __syncthreads();

        const int s = c & 1;
        uint32_t aH = sb + s * STAGE, aL = aH + APL, bW = sb + s * STAGE + P * APL;
        #pragma unroll
        for (int kk = 0; kk < 4; kk++) {
            const uint32_t aRow = (uint32_t)(wm * 64 + ((lane >> 3) & 1) * 8 + r8);
            const uint32_t aCol = (uint32_t)(kk * 32 + ((lane >> 4) & 1) * 16);
            uint32_t ah[4][4], al[4][4];
            #pragma unroll
            for (int mt = 0; mt < 4; mt++) {
                uint32_t ad = (aRow + mt * 16) * 144 + aCol;
                LDSM4(ah[mt][0], ah[mt][1], ah[mt][2], ah[mt][3], aH + ad);
                if (P == 2) LDSM4(al[mt][0], al[mt][1], al[mt][2], al[mt][3], aL + ad);
            }
            uint32_t bh[NPAIR][4];
            const uint32_t bCol = (uint32_t)(kk * 32 + ((lane >> 3) & 1) * 16);
            #pragma unroll
            for (int np = 0; np < NPAIR; np++) {
                uint32_t bRow = (uint32_t)(wn * (BN / 2) + np * 16 + ((lane >> 4) & 1) * 8 + r8);
                LDSM4(bh[np][0], bh[np][1], bh[np][2], bh[np][3], bW + bRow * 144 + bCol);
            }
            #pragma unroll
            for (int np = 0; np < NPAIR; np++) {
                #pragma unroll
                for (int sd = 0; sd < 2; sd++) {
                    int nt = np * 2 + sd;
                    #pragma unroll
                    for (int mt = 0; mt < 4; mt++) {
                        mma4(acc[mt][nt], ah[mt], bh[np][sd * 2], bh[np][sd * 2 + 1]);
                        if (P == 2)
                            mma4(acc[mt][nt], al[mt], bh[np][sd * 2], bh[np][sd * 2 + 1]);
                    }
                }
            }
        }
        __syncthreads();
    }

    #pragma unroll
    for (int mt = 0; mt < 4; mt++) {
        #pragma unroll
        for (int nt = 0; nt < WNT; nt++) {
            int gm = m0 + wm * 64 + mt * 16 + lq;
            int gn = n0 + wn * (BN / 2) + nt * 8 + lr * 2;
            float* a = acc[mt][nt];
            if (MODE == 0) {
                float2 v0; v0.x = a[0]; v0.y = a[1];
                float2 v1; v1.x = a[2]; v1.y = a[3];
                *reinterpret_cast<float2*>(p.C + (size_t)gm * p.ldc + gn) = v0;
                *reinterpret_cast<float2*>(p.C + (size_t)(gm + 8) * p.ldc + gn) = v1;
            } else {
                float b0 = p.bias[gn], b1 = p.bias[gn + 1];
                float v00 = tanhf(a[0] + b0), v01 = tanhf(a[1] + b1);
                float v10 = tanhf(a[2] + b0), v11 = tanhf(a[3] + b1);
                __half2 h0, l0, h1, l1;
                split2(v00, h0.x, l0.x); split2(v01, h0.y, l0.y);
                split2(v10, h1.x, l1.x); split2(v11, h1.y, l1.y);
                size_t row0, row1;
                if (MODE == 2) {
                    row0 = (size_t)(2 * (gm & 31) + p.par) * NB + (gm >> 5);
                    row1 = (size_t)(2 * ((gm + 8) & 31) + p.par) * NB + ((gm + 8) >> 5);
                } else {
                    row0 = (size_t)gm; row1 = (size_t)(gm + 8);
                }
                *reinterpret_cast<__half2*>(p.Ohi + row0 * p.ldo + gn) = h0;
                *reinterpret_cast<__half2*>(p.Olo + row0 * p.ldo + gn) = l0;
                *reinterpret_cast<__half2*>(p.Ohi + row1 * p.ldo + gn) = h1;
                *reinterpret_cast<__half2*>(p.Olo + row1 * p.ldo + gn) = l1;
                if (MODE == 3) {
                    float2 v0; v0.x = v00; v0.y = v01;
                    float2 v1; v1.x = v10; v1.y = v11;
                    *reinterpret_cast<float2*>(p.C + (size_t)gm * p.ldc + gn) = v0;
                    *reinterpret_cast<float2*>(p.C + (size_t)(gm + 8) * p.ldc + gn) = v1;
                }
            }
        }
    }
}

// ------------------- fused GRU step: gh GEMM (+gi GEMM) + gates ----------------
__device__ __forceinline__ void gs_compute(uint32_t aH, uint32_t aL, uint32_t bW,
                                           int wn, int lane, int kk, float (*acc)[3][4])
{
    const int r8 = lane & 7;
    const uint32_t aRow = (uint32_t)(((lane >> 3) & 1) * 8 + r8);
    const uint32_t aCol = (uint32_t)(kk * 32 + ((lane >> 4) & 1) * 16);
    uint32_t ah[4][4], al[4][4];
    #pragma unroll
    for (int mt = 0; mt < 4; mt++) {
        uint32_t ad = (aRow + mt * 16) * 144 + aCol;
        LDSM4(ah[mt][0], ah[mt][1], ah[mt][2], ah[mt][3], aH + ad);
        LDSM4(al[mt][0], al[mt][1], al[mt][2], al[mt][3], aL + ad);
    }
    uint32_t bh[6];
    const uint32_t bCol = (uint32_t)(kk * 32 + ((lane >> 3) & 1) * 16);
    {
        uint32_t bRow = (uint32_t)(wn * 24 + ((lane >> 4) & 1) * 8 + r8);
        LDSM4(bh[0], bh[1], bh[2], bh[3], bW + bRow * 144 + bCol);
    }
    {
        uint32_t bRow = (uint32_t)(wn * 24 + 16 + r8);
        LDSM2(bh[4], bh[5], bW + bRow * 144 + bCol);
    }
    #pragma unroll
    for (int nt = 0; nt < 3; nt++) {
        uint32_t b0 = bh[nt * 2], b1 = bh[nt * 2 + 1];
        #pragma unroll
        for (int mt = 0; mt < 4; mt++) {
            mma4(acc[mt][nt], ah[mt], b0, b1);
            mma4(acc[mt][nt], al[mt], b0, b1);
        }
    }
}

template<int DUAL, int WSEQ>
__global__ __launch_bounds__(128)
void gru_step(const hf* __restrict__ Hh, const hf* __restrict__ Hl,
              const hf* __restrict__ Wh,
              const hf* __restrict__ Xh, const hf* __restrict__ Xl,
              const hf* __restrict__ Wi,
              const float* __restrict__ giB, long giS,
              const float* __restrict__ bih, const float* __restrict__ bhh,
              const float* __restrict__ hOld,
              float* __restrict__ hNew, hf* __restrict__ nhi, hf* __restrict__ nlo,
              hf* __restrict__ shi, hf* __restrict__ slo)
{
    extern __shared__ __align__(16) char sm[];
    constexpr int APL = 64 * 144, BPL = 96 * 144;
    constexpr int NPA = DUAL ? 4 : 2;
    constexpr int NPB = DUAL ? 2 : 1;
    constexpr int STAGE = NPA * APL + NPB * BPL;

    const int tid = threadIdx.x, lane = tid & 31, wn = tid >> 5;
    const int lq = lane >> 2, lr = lane & 3;
    const int f0 = blockIdx.x * 32, m0 = blockIdx.y * 64;
    const uint32_t sb = smem_u32(sm);

    float acch[4][3][4];
    float acci[4][3][4];
    #pragma unroll
    for (int i = 0; i < 4; i++)
        #pragma unroll
        for (int j = 0; j < 3; j++)
            #pragma unroll
            for (int q = 0; q < 4; q++) { acch[i][j][q] = 0.f; acci[i][j][q] = 0.f; }

    auto load_stage = [&](int s, int k0) {
        uint32_t base = sb + s * STAGE;
        #pragma unroll
        for (int v = tid; v < 512; v += 128) {
            int row = v >> 3, q = v & 7;
            size_t g = (size_t)(m0 + row) * NF + k0 + q * 8;
            uint32_t d = base + row * 144 + q * 16;
            CPA(d, Hh + g);
            CPA(d + APL, Hl + g);
            if (DUAL) { CPA(d + 2 * APL, Xh + g); CPA(d + 3 * APL, Xl + g); }
        }
        uint32_t bb = base + NPA * APL;
        #pragma unroll
        for (int v = tid; v < 768; v += 128) {
            int rr = v >> 3, q8 = v & 7;
            int qq = rr / 24, rem = rr - qq * 24;
            int g = rem >> 3, u = rem & 7;
            size_t R = (size_t)(g * 1024 + f0 + qq * 8 + u) * NF + k0 + q8 * 8;
            uint32_t d = bb + rr * 144 + q8 * 16;
            CPA(d, Wh + R);
            if (DUAL) CPA(d + BPL, Wi + R);
        }
    };

    const int NC = NF >> 6;          // 16
    load_stage(0, 0);
    CPA_COMMIT();

    for (int c = 0; c < NC; c++) {
        if (c + 1 < NC) { load_stage((c + 1) & 1, (c + 1) << 6); CPA_COMMIT(); CPA_WAIT1(); }
        else           { CPA_WAIT0(); }
        __syncthreads();

        uint32_t base = sb + (c & 1) * STAGE;
        uint32_t bb = base + NPA * APL;
        #pragma unroll
        for (int kk = 0; kk < 4; kk++) {
            gs_compute(base, base + APL, bb, wn, lane, kk, acch);
            if (DUAL)
                gs_compute(base + 2 * APL, base + 3 * APL, bb + BPL, wn, lane, kk, acci);
        }
        __syncthreads();
    }

    // ---- fused GRU gate epilogue ----
    const int fc = f0 + wn * 8 + lr * 2;
    float bi[3][2], bh_[3][2];
    #pragma unroll
    for (int g = 0; g < 3; g++) {
        bi[g][0]  = bih[g * 1024 + fc];  bi[g][1]  = bih[g * 1024 + fc + 1];
        bh_[g][0] = bhh[g * 1024 + fc];  bh_[g][1] = bhh[g * 1024 + fc + 1];
    }
    #pragma unroll
    for (int mt = 0; mt < 4; mt++) {
        #pragma unroll
        for (int half = 0; half < 2; half++) {
            int b = m0 + mt * 16 + lq + half * 8;
            float o[2];
            #pragma unroll
            for (int cidx = 0; cidx < 2; cidx++) {
                int k = half * 2 + cidx;
                int f = fc + cidx;
                float hr = acch[mt][0][k], hz = acch[mt][1][k], hn = acch[mt][2][k];
                float ir, iz, in_;
                if (DUAL) {
                    ir = acci[mt][0][k]; iz = acci[mt][1][k]; in_ = acci[mt][2][k];
                } else {
                    const float* gp = giB + (size_t)b * giS;
                    ir = gp[f]; iz = gp[1024 + f]; in_ = gp[2048 + f];
                }
                float r = 1.f / (1.f + expf(-(ir + bi[0][cidx] + hr + bh_[0][cidx])));
                float z = 1.f / (1.f + expf(-(iz + bi[1][cidx] + hz + bh_[1][cidx])));
                float n = tanhf(in_ + bi[2][cidx] + r * (hn + bh_[2][cidx]));
                float ho = hOld[(size_t)b * NF + f];
                o[cidx] = (1.f - z) * n + z * ho;
            }
            float2 o2; o2.x = o[0]; o2.y = o[1];
            *reinterpret_cast<float2*>(hNew + (size_t)b * NF + fc) = o2;
            __half2 hh, ll;
            split2(o[0], hh.x, ll.x);
            split2(o[1], hh.y, ll.y);
            *reinterpret_cast<__half2*>(nhi + (size_t)b * NF + fc) = hh;
            *reinterpret_cast<__half2*>(nlo + (size_t)b * NF + fc) = ll;
            if (WSEQ) {
                *reinterpret_cast<__half2*>(shi + (size_t)b * NF + fc) = hh;
                *reinterpret_cast<__half2*>(slo + (size_t)b * NF + fc) = ll;
            }
        }
    }
}

// ------------------------------ small kernels ----------------------------------
struct SA {
    const float* s[9];
    hf *hi[9], *lo[9];      // lo == null -> single-precision convert only
    long n[9];
    float* H;
    hf *Hh, *Hl;
    long total;
};

__global__ void split_all_k(SA a)
{
    long i = (long)blockIdx.x * blockDim.x + threadIdx.x;
    long stride = (long)gridDim.x * blockDim.x;
    for (; i < a.total; i += stride) {
        long r = i;
        int seg = 0;
        while (seg < 9 && r >= a.n[seg]) { r -= a.n[seg]; seg++; }
        if (seg < 9) {
            float v = a.s[seg][r];
            hf h = __float2half_rn(v);
            a.hi[seg][r] = h;
            if (a.lo[seg]) a.lo[seg][r] = __float2half_rn(v - __half2float(h));
        } else {
            a.H[r] = 0.f;
            a.Hh[r] = __float2half_rn(0.f);
            a.Hl[r] = __float2half_rn(0.f);
        }
    }
}

__global__ void rproj_k(const float* __restrict__ H1, const float* __restrict__ Wr,
                        const float* __restrict__ br, float* __restrict__ out_r, int step)
{
    __shared__ float red[256];
    int b = blockIdx.x;
    float p = 0.f;
    for (int k = threadIdx.x; k < NF; k += 256) p += H1[(size_t)b * NF + k] * Wr[k];
    red[threadIdx.x] = p;
    __syncthreads();
    for (int s = 128; s > 0; s >>= 1) {
        if (threadIdx.x < s) red[threadIdx.x] += red[threadIdx.x + s];
        __syncthreads();
    }
    if (threadIdx.x == 0)
        out_r[b * NTF + step] = 1.f / (1.f + expf(-(red[0] + br[0])));
}

// ----------------------------------- host --------------------------------------
static const int SM128P1 = 2 * (128 * 144 + 128 * 144);       // 73728
static const int SM64P1  = 2 * (128 * 144 +  64 * 144);       // 55296
static const int SMS     = 2 * (2 * 64 * 144 + 96 * 144);     // 64512
static const int SMD     = 2 * (4 * 64 * 144 + 2 * 96 * 144); // 129024

static inline GP mkGP(const hf* Ah, const hf* Al, long lda, const hf* W,
                      const float* bias, float* C, long ldc,
                      hf* Ohi, hf* Olo, long ldo, long K, int par = 0)
{
    GP p; p.Ah = Ah; p.Al = Al; p.W = W; p.bias = bias;
    p.C = C; p.Ohi = Ohi; p.Olo = Olo; p.lda = lda; p.ldc = ldc; p.ldo = ldo;
    p.K = K; p.par = par;
    return p;
}

extern "C" void kernel_launch(void* const* d_in, const int* in_sizes, int n_in,
                              void* d_out, int out_size)
{
    (void)in_sizes; (void)n_in; (void)out_size;
    const float* history_s = (const float*)d_in[0];
    const float* history_a = (const float*)d_in[1];
    const float* present_s = (const float*)d_in[2];
    const float* future_a  = (const float*)d_in[3];
    const float* Ws  = (const float*)d_in[4];
    const float* bs  = (const float*)d_in[5];
    const float* Wa  = (const float*)d_in[6];
    const float* ba  = (const float*)d_in[7];
    const float* Wih = (const float*)d_in[8];
    const float* Whh = (const float*)d_in[9];
    const float* bih = (const float*)d_in[10];
    const float* bhh = (const float*)d_in[11];
    const float* Wr  = (const float*)d_in[12];
    const float* br  = (const float*)d_in[13];
    const float* Ws2 = (const float*)d_in[14];
    const float* bs2 = (const float*)d_in[15];

    float* out_r = (float*)d_out;
    float* out_s = (float*)d_out + NB * NTF;

    float *gi, *fxg, *H;
    hf *Hhi, *Hlo, *xshi, *xslo, *seqhi, *seqlo, *xhi, *xlo, *fxhi, *fxlo, *sohi, *solo;
    hf *hshi, *hslo, *hahi, *halo, *pshi, *pslo, *fahi, *falo;
    hf *Wsh, *Wah, *Wihh, *Whhh, *Ws2h;
    cudaGetSymbolAddress((void**)&gi, g_gi);     cudaGetSymbolAddress((void**)&fxg, g_fxg);
    cudaGetSymbolAddress((void**)&H, g_H);
    cudaGetSymbolAddress((void**)&Hhi, g_H_hi);  cudaGetSymbolAddress((void**)&Hlo, g_H_lo);
    cudaGetSymbolAddress((void**)&xshi, g_xs_hi); cudaGetSymbolAddress((void**)&xslo, g_xs_lo);
    cudaGetSymbolAddress((void**)&seqhi, g_seq_hi); cudaGetSymbolAddress((void**)&seqlo, g_seq_lo);
    cudaGetSymbolAddress((void**)&xhi, g_x_hi);  cudaGetSymbolAddress((void**)&xlo, g_x_lo);
    cudaGetSymbolAddress((void**)&fxhi, g_fx_hi); cudaGetSymbolAddress((void**)&fxlo, g_fx_lo);
    cudaGetSymbolAddress((void**)&sohi, g_so_hi); cudaGetSymbolAddress((void**)&solo, g_so_lo);
    cudaGetSymbolAddress((void**)&hshi, g_hs_hi); cudaGetSymbolAddress((void**)&hslo, g_hs_lo);
    cudaGetSymbolAddress((void**)&hahi, g_ha_hi); cudaGetSymbolAddress((void**)&halo, g_ha_lo);
    cudaGetSymbolAddress((void**)&pshi, g_ps_hi); cudaGetSymbolAddress((void**)&pslo, g_ps_lo);
    cudaGetSymbolAddress((void**)&fahi, g_fa_hi); cudaGetSymbolAddress((void**)&falo, g_fa_lo);
    cudaGetSymbolAddress((void**)&Wsh, g_Ws_h);
    cudaGetSymbolAddress((void**)&Wah, g_Wa_h);
    cudaGetSymbolAddress((void**)&Wihh, g_Wih_h);
    cudaGetSymbolAddress((void**)&Whhh, g_Whh_h);
    cudaGetSymbolAddress((void**)&Ws2h, g_Ws2_h);

    cudaFuncSetAttribute(mma_gemm<128, 0, 1>, cudaFuncAttributeMaxDynamicSharedMemorySize, SM128P1);
    cudaFuncSetAttribute(mma_gemm<128, 1, 1>, cudaFuncAttributeMaxDynamicSharedMemorySize, SM128P1);
    cudaFuncSetAttribute(mma_gemm<128, 2, 1>, cudaFuncAttributeMaxDynamicSharedMemorySize, SM128P1);
    cudaFuncSetAttribute(mma_gemm<64, 0, 1>,  cudaFuncAttributeMaxDynamicSharedMemorySize, SM64P1);
    cudaFuncSetAttribute(mma_gemm<64, 1, 1>,  cudaFuncAttributeMaxDynamicSharedMemorySize, SM64P1);
    cudaFuncSetAttribute(mma_gemm<64, 3, 1>,  cudaFuncAttributeMaxDynamicSharedMemorySize, SM64P1);
    cudaFuncSetAttribute(gru_step<0, 0>, cudaFuncAttributeMaxDynamicSharedMemorySize, SMS);
    cudaFuncSetAttribute(gru_step<0, 1>, cudaFuncAttributeMaxDynamicSharedMemorySize, SMS);
    cudaFuncSetAttribute(gru_step<1, 0>, cudaFuncAttributeMaxDynamicSharedMemorySize, SMD);

    // ---- 1: merged split + zeroH ----
    {
        SA a;
        const float* srcs[9] = { history_s, history_a, present_s, future_a,
                                 Ws, Wa, Wih, Whh, Ws2 };
        hf* his[9] = { hshi, hahi, pshi, fahi, Wsh, Wah, Wihh, Whhh, Ws2h };
        hf* los[9] = { hslo, halo, pslo, falo, nullptr, nullptr, nullptr, nullptr, nullptr };
        long ns[9] = { (long)NB * NTH * NS, (long)NB * NTH * NA, (long)NB * NS,
                       (long)NB * NTF * NA, (long)NF * NS, (long)NF * NA,
                       (long)2 * NG * NF, (long)2 * NG * NF, (long)NS * NF };
        long tot = 0;
        for (int k = 0; k < 9; k++) { a.s[k] = srcs[k]; a.hi[k] = his[k]; a.lo[k] = los[k]; a.n[k] = ns[k]; tot += ns[k]; }
        a.H = H; a.Hh = Hhi; a.Hl = Hlo;
        a.total = tot + (long)4 * NB * NF;
        split_all_k<<<4096, 256>>>(a);
    }

    const hf *Wih0 = Wihh, *Wih1 = Wihh + (size_t)NG * NF;
    const hf *Whh0 = Whhh, *Whh1 = Whhh + (size_t)NG * NF;
    const float *bih0 = bih, *bih1 = bih + NG, *bhh0 = bhh, *bhh1 = bhh + NG;

    auto Hf  = [&](int l, int p) { return H   + (size_t)(l * 2 + p) * NB * NF; };
    auto Hfh = [&](int l, int p) { return Hhi + (size_t)(l * 2 + p) * NB * NF; };
    auto Hfl = [&](int l, int p) { return Hlo + (size_t)(l * 2 + p) * NB * NF; };
    int p0 = 0, p1 = 0;

    const dim3 GS(NF / 32, NB / 64);       // (32, 4) = 128 CTAs

    // ---- 2: dual embedding (s + a) with fused prefix scatter ----
    {   GP pS = mkGP(hshi, hslo, NS, Wsh, bs, nullptr, 0, xshi, xslo, NF, NS, 0);
        GP pA = mkGP(hahi, halo, NA, Wah, ba, nullptr, 0, xshi, xslo, NF, NA, 1);
        mma_gemm<128, 2, 1><<<dim3(NF / 128, (NB * NTH) / 128, 2), 128, SM128P1>>>(pS, pA); }

    // ---- 3: hoisted layer-0 gi over prefix slots 0..63 ----
    {   GP p = mkGP(xshi, xslo, NF, Wih0, nullptr, gi, NG, nullptr, nullptr, 0, NF);
        mma_gemm<128, 0, 1><<<dim3(NG / 128, (64 * NB) / 128, 1), 128, SM128P1>>>(p, p); }

    // ---- 4: first GRU step (ncu capture target) ----
    gru_step<0, 1><<<GS, 128, SMS>>>(Hfh(0, p0), Hfl(0, p0), Whh0,
        nullptr, nullptr, nullptr,
        gi, (long)NG, bih0, bhh0,
        Hf(0, p0), Hf(0, p0 ^ 1), Hfh(0, p0 ^ 1), Hfl(0, p0 ^ 1),
        seqhi, seqlo);
    p0 ^= 1;

    // ---- 5,6: present embedding -> xs slot 64, and its gi ----
    {   GP p = mkGP(pshi, pslo, NS, Wsh, bs, nullptr, 0,
                    xshi + (size_t)64 * NB * NF, xslo + (size_t)64 * NB * NF, NF, NS);
        mma_gemm<64, 1, 1><<<dim3(NF / 64, NB / 128, 1), 128, SM64P1>>>(p, p); }
    {   GP p = mkGP(xshi + (size_t)64 * NB * NF, xslo + (size_t)64 * NB * NF, NF,
                    Wih0, nullptr, gi + (size_t)64 * NB * NG, NG, nullptr, nullptr, 0, NF);
        mma_gemm<64, 0, 1><<<dim3(NG / 64, NB / 128, 1), 128, SM64P1>>>(p, p); }

    // ---- layer 0 over remaining prefix ----
    for (int t = 1; t < NT; t++) {
        gru_step<0, 1><<<GS, 128, SMS>>>(Hfh(0, p0), Hfl(0, p0), Whh0,
            nullptr, nullptr, nullptr,
            gi + (size_t)t * NB * NG, (long)NG, bih0, bhh0,
            Hf(0, p0), Hf(0, p0 ^ 1), Hfh(0, p0 ^ 1), Hfl(0, p0 ^ 1),
            seqhi + (size_t)t * NB * NF, seqlo + (size_t)t * NB * NF);
        p0 ^= 1;
    }

    // ---- future action embeddings + hoisted gi ----
    {   GP p = mkGP(fahi, falo, NA, Wah, ba, nullptr, 0, fxhi, fxlo, NF, NA);
        mma_gemm<128, 1, 1><<<dim3(NF / 128, (NB * NTF) / 128, 1), 128, SM128P1>>>(p, p); }
    {   GP p = mkGP(fxhi, fxlo, NF, Wih0, nullptr, fxg, NG, nullptr, nullptr, 0, NF);
        mma_gemm<128, 0, 1><<<dim3(NG / 128, (NB * NTF) / 128, 1), 128, SM128P1>>>(p, p); }

    // ---- layer 1 over prefix ----
    {   GP p = mkGP(seqhi, seqlo, NF, Wih1, nullptr, gi, NG, nullptr, nullptr, 0, NF);
        mma_gemm<128, 0, 1><<<dim3(NG / 128, (NT * NB) / 128, 1), 128, SM128P1>>>(p, p); }
    for (int t = 0; t < NT; t++) {
        gru_step<0, 0><<<GS, 128, SMS>>>(Hfh(1, p1), Hfl(1, p1), Whh1,
            nullptr, nullptr, nullptr,
            gi + (size_t)t * NB * NG, (long)NG, bih1, bhh1,
            Hf(1, p1), Hf(1, p1 ^ 1), Hfh(1, p1 ^ 1), Hfl(1, p1 ^ 1),
            nullptr, nullptr);
        p1 ^= 1;
    }

    auto dcell = [&](const hf* Xh, const hf* Xl, int layer) {
        int& pp = layer ? p1 : p0;
        gru_step<1, 0><<<GS, 128, SMD>>>(
            Hfh(layer, pp), Hfl(layer, pp),
            layer ? Whh1 : Whh0,
            Xh, Xl, layer ? Wih1 : Wih0,
            nullptr, 0, layer ? bih1 : bih0, layer ? bhh1 : bhh0,
            Hf(layer, pp), Hf(layer, pp ^ 1), Hfh(layer, pp ^ 1), Hfl(layer, pp ^ 1),
            nullptr, nullptr);
        pp ^= 1;
    };

    // ---- future rollout ----
    for (int i = 0; i < NTF; i++) {
        gru_step<0, 0><<<GS, 128, SMS>>>(Hfh(0, p0), Hfl(0, p0), Whh0,
            nullptr, nullptr, nullptr,
            fxg + (size_t)i * NG, (long)NTF * NG, bih0, bhh0,
            Hf(0, p0), Hf(0, p0 ^ 1), Hfh(0, p0 ^ 1), Hfl(0, p0 ^ 1),
            nullptr, nullptr);
        p0 ^= 1;
        dcell(Hfh(0, p0), Hfl(0, p0), 1);

        rproj_k<<<NB, 256>>>(Hf(1, p1), Wr, br, out_r, i);
        {   GP p = mkGP(Hfh(1, p1), Hfl(1, p1), NF, Ws2h, bs2,
                        out_s + (size_t)i * NS, (long)NTF * NS, sohi, solo, NS, NF);
            mma_gemm<64, 3, 1><<<dim3(NS / 64, NB / 128, 1), 128, SM64P1>>>(p, p); }
        {   GP p = mkGP(sohi, solo, NS, Wsh, bs, nullptr, 0, xhi, xlo, NF, NS);
            mma_gemm<64, 1, 1><<<dim3(NF / 64, NB / 128, 1), 128, SM64P1>>>(p, p); }
        dcell(xhi, xlo, 0);
        dcell(Hfh(0, p0), Hfl(0, p0), 1);
    }
}